// round 2
// baseline (speedup 1.0000x reference)
#include <cuda_runtime.h>
#include <math.h>

// Problem constants
#define BB     4
#define SENC   2048
#define SDEC   1024
#define DIM    1024
#define NH     16
#define HD     64
#define SCALE_INV (0.125f)   // 1/sqrt(64)

// Scratch (static device globals — allocation-free)
__device__ float g_Q[BB * SDEC * DIM];   // 16 MB
__device__ float g_K[BB * SENC * DIM];   // 32 MB
__device__ float g_V[BB * SENC * DIM];   // 32 MB
__device__ float g_X[BB * SDEC * DIM];   // 16 MB

// ---------------------------------------------------------------------------
// SGEMM: C[M,N] = A[M,K] @ W[K,N] + bias[N]
// Block tile 128x64, BK=8, thread tile 8x4, 256 threads.
// ---------------------------------------------------------------------------
#define GBM 128
#define GBN 64
#define GBK 8
#define GTM 8
#define GTN 4

__global__ __launch_bounds__(256) void sgemm_bias_kernel(
    const float* __restrict__ A, const float* __restrict__ W,
    const float* __restrict__ bias, float* __restrict__ C,
    int M, int N, int K)
{
    __shared__ float As[GBK][GBM];   // transposed A tile
    __shared__ float Bs[GBK][GBN];

    const int t  = threadIdx.x;
    const int bm = blockIdx.y * GBM;
    const int bn = blockIdx.x * GBN;

    const int tr = t / 16;   // 0..15 -> rows tr*8..tr*8+7
    const int tc = t % 16;   // 0..15 -> cols tc*4..tc*4+3

    // A tile loader: 128 rows x 8 cols, float4 per thread
    const int arow = t >> 1;
    const int acol = (t & 1) * 4;
    // B tile loader: 8 rows x 64 cols, float2 per thread
    const int brow = t >> 5;          // 0..7
    const int bcol = (t & 31) * 2;    // 0..62

    const float* Aptr = A + (size_t)(bm + arow) * K + acol;
    const float* Wptr = W + (size_t)brow * N + bn + bcol;

    float acc[GTM][GTN];
#pragma unroll
    for (int i = 0; i < GTM; i++)
#pragma unroll
        for (int j = 0; j < GTN; j++) acc[i][j] = 0.f;

    for (int k0 = 0; k0 < K; k0 += GBK) {
        float4 a4 = *(const float4*)(Aptr + k0);
        float2 b2 = *(const float2*)(Wptr + (size_t)k0 * N);
        As[acol + 0][arow] = a4.x;
        As[acol + 1][arow] = a4.y;
        As[acol + 2][arow] = a4.z;
        As[acol + 3][arow] = a4.w;
        Bs[brow][bcol + 0] = b2.x;
        Bs[brow][bcol + 1] = b2.y;
        __syncthreads();

#pragma unroll
        for (int k = 0; k < GBK; k++) {
            float ra[GTM], rb[GTN];
#pragma unroll
            for (int i = 0; i < GTM; i++) ra[i] = As[k][tr * GTM + i];
            float4 b4 = *(const float4*)&Bs[k][tc * GTN];
            rb[0] = b4.x; rb[1] = b4.y; rb[2] = b4.z; rb[3] = b4.w;
#pragma unroll
            for (int i = 0; i < GTM; i++)
#pragma unroll
                for (int j = 0; j < GTN; j++)
                    acc[i][j] += ra[i] * rb[j];
        }
        __syncthreads();
    }

    // Epilogue: bias + store (float4 per row)
    const int colbase = bn + tc * GTN;
    float4 bv = *(const float4*)&bias[colbase];
#pragma unroll
    for (int i = 0; i < GTM; i++) {
        int row = bm + tr * GTM + i;
        float4 o;
        o.x = acc[i][0] + bv.x;
        o.y = acc[i][1] + bv.y;
        o.z = acc[i][2] + bv.z;
        o.w = acc[i][3] + bv.w;
        *(float4*)&C[(size_t)row * N + colbase] = o;
    }
}

// ---------------------------------------------------------------------------
// Flash attention (fp32): per block = one (b, h, 64-row q tile).
// Online softmax over S_ENC in 64-col tiles.
// Mask is read as 32-bit words: nonzero bits == masked. This is correct
// whether the harness materialized the bool as int32 (1) or float32 (1.0f).
// ---------------------------------------------------------------------------
#define BQ  64
#define BKT 64
#define PAD 68
#define ATTN_SMEM (4 * BQ * PAD * (int)sizeof(float))  // Qs,Ks,Vs,Ps = 69632 B

__global__ __launch_bounds__(256) void attn_kernel(
    const unsigned int* __restrict__ mask, float* __restrict__ X)
{
    extern __shared__ float sm[];
    float* Qs = sm;                    // [d][r]  64 x 68
    float* Ks = sm + BQ * PAD;         // [d][c]
    float* Vs = sm + 2 * BQ * PAD;     // [c][dv]
    float* Ps = sm + 3 * BQ * PAD;     // [r][c]

    const int qt = blockIdx.x;     // 0..15
    const int h  = blockIdx.y;     // 0..15
    const int b  = blockIdx.z;     // 0..3
    const int t  = threadIdx.x;
    const int tr = t / 16;         // row group: rows tr*4..tr*4+3
    const int tc = t % 16;         // col group: cols tc*4..tc*4+3
    const int q0 = qt * BQ;

    const float* Qg = g_Q + ((size_t)(b * SDEC + q0)) * DIM + h * HD;
    const float* Kg = g_K + ((size_t)b * SENC) * DIM + h * HD;
    const float* Vg = g_V + ((size_t)b * SENC) * DIM + h * HD;
    const unsigned int* mk = mask + (size_t)b * SENC;   // one 32-bit word per key

    // Load Q tile transposed: Qs[d][r]
#pragma unroll
    for (int it = 0; it < 4; it++) {
        int idx = (t + it * 256) * 4;     // 0..4092
        int r = idx >> 6;
        int d = idx & 63;
        float4 v = *(const float4*)(Qg + (size_t)r * DIM + d);
        Qs[(d + 0) * PAD + r] = v.x;
        Qs[(d + 1) * PAD + r] = v.y;
        Qs[(d + 2) * PAD + r] = v.z;
        Qs[(d + 3) * PAD + r] = v.w;
    }

    float m[4], l[4], o[4][4];
#pragma unroll
    for (int i = 0; i < 4; i++) {
        m[i] = -1e30f; l[i] = 0.f;
#pragma unroll
        for (int j = 0; j < 4; j++) o[i][j] = 0.f;
    }

    for (int k0 = 0; k0 < SENC; k0 += BKT) {
        __syncthreads();  // previous iter's Ps/Vs reads complete

        // Load K tile transposed (Ks[d][c]) and V tile (Vs[c][dv])
#pragma unroll
        for (int it = 0; it < 4; it++) {
            int idx = (t + it * 256) * 4;
            int c = idx >> 6;
            int d = idx & 63;
            float4 kv = *(const float4*)(Kg + (size_t)(k0 + c) * DIM + d);
            Ks[(d + 0) * PAD + c] = kv.x;
            Ks[(d + 1) * PAD + c] = kv.y;
            Ks[(d + 2) * PAD + c] = kv.z;
            Ks[(d + 3) * PAD + c] = kv.w;
            float4 vv = *(const float4*)(Vg + (size_t)(k0 + c) * DIM + d);
            *(float4*)&Vs[c * PAD + d] = vv;
        }
        __syncthreads();

        // S = Q @ K^T (thread computes 4x4)
        float s[4][4];
#pragma unroll
        for (int i = 0; i < 4; i++)
#pragma unroll
            for (int j = 0; j < 4; j++) s[i][j] = 0.f;

#pragma unroll
        for (int d = 0; d < HD; d++) {
            float ra[4];
#pragma unroll
            for (int i = 0; i < 4; i++) ra[i] = Qs[d * PAD + tr * 4 + i];
            float4 kb = *(const float4*)&Ks[d * PAD + tc * 4];
#pragma unroll
            for (int i = 0; i < 4; i++) {
                s[i][0] += ra[i] * kb.x;
                s[i][1] += ra[i] * kb.y;
                s[i][2] += ra[i] * kb.z;
                s[i][3] += ra[i] * kb.w;
            }
        }

        // scale + mask (nonzero 32-bit word == masked)
#pragma unroll
        for (int j = 0; j < 4; j++) {
            bool msk = (mk[k0 + tc * 4 + j] != 0u);
#pragma unroll
            for (int i = 0; i < 4; i++)
                s[i][j] = msk ? -1e30f : s[i][j] * SCALE_INV;
        }

        // online softmax: row reductions across the 16 tc-lanes (half-warp)
#pragma unroll
        for (int i = 0; i < 4; i++) {
            float v = fmaxf(fmaxf(s[i][0], s[i][1]), fmaxf(s[i][2], s[i][3]));
#pragma unroll
            for (int off = 1; off < 16; off <<= 1)
                v = fmaxf(v, __shfl_xor_sync(0xffffffffu, v, off));
            float mnew = fmaxf(m[i], v);
            float alpha = __expf(m[i] - mnew);
            float rs = 0.f;
#pragma unroll
            for (int j = 0; j < 4; j++) {
                float p = __expf(s[i][j] - mnew);
                s[i][j] = p;
                rs += p;
            }
#pragma unroll
            for (int off = 1; off < 16; off <<= 1)
                rs += __shfl_xor_sync(0xffffffffu, rs, off);
            l[i] = l[i] * alpha + rs;
            m[i] = mnew;
#pragma unroll
            for (int j = 0; j < 4; j++) o[i][j] *= alpha;
        }

        // P -> smem
#pragma unroll
        for (int i = 0; i < 4; i++) {
            float4 pv = make_float4(s[i][0], s[i][1], s[i][2], s[i][3]);
            *(float4*)&Ps[(tr * 4 + i) * PAD + tc * 4] = pv;
        }
        __syncthreads();

        // O += P @ V
#pragma unroll 8
        for (int c = 0; c < BKT; c++) {
            float4 v4 = *(const float4*)&Vs[c * PAD + tc * 4];
            float rp[4];
#pragma unroll
            for (int i = 0; i < 4; i++) rp[i] = Ps[(tr * 4 + i) * PAD + c];
#pragma unroll
            for (int i = 0; i < 4; i++) {
                o[i][0] += rp[i] * v4.x;
                o[i][1] += rp[i] * v4.y;
                o[i][2] += rp[i] * v4.z;
                o[i][3] += rp[i] * v4.w;
            }
        }
    }

    // Normalize and write X[b, q0+r, h*64 + dv]
#pragma unroll
    for (int i = 0; i < 4; i++) {
        int r = tr * 4 + i;
        float inv = 1.0f / l[i];
        float4 ov = make_float4(o[i][0] * inv, o[i][1] * inv,
                                o[i][2] * inv, o[i][3] * inv);
        *(float4*)&X[((size_t)(b * SDEC + q0 + r)) * DIM + h * HD + tc * 4] = ov;
    }
}

// ---------------------------------------------------------------------------
// Launch
// Inputs (metadata order): enc, enc_mask, dec, q_w, q_b, k_w, k_b, v_w, v_b, o_w, o_b
// ---------------------------------------------------------------------------
extern "C" void kernel_launch(void* const* d_in, const int* in_sizes, int n_in,
                              void* d_out, int out_size)
{
    const float*        enc      = (const float*)d_in[0];
    const unsigned int* enc_mask = (const unsigned int*)d_in[1];
    const float*        dec      = (const float*)d_in[2];
    const float*        q_w      = (const float*)d_in[3];
    const float*        q_b      = (const float*)d_in[4];
    const float*        k_w      = (const float*)d_in[5];
    const float*        k_b      = (const float*)d_in[6];
    const float*        v_w      = (const float*)d_in[7];
    const float*        v_b      = (const float*)d_in[8];
    const float*        o_w      = (const float*)d_in[9];
    const float*        o_b      = (const float*)d_in[10];
    float*              out      = (float*)d_out;

    float *pQ, *pK, *pV, *pX;
    cudaGetSymbolAddress((void**)&pQ, g_Q);
    cudaGetSymbolAddress((void**)&pK, g_K);
    cudaGetSymbolAddress((void**)&pV, g_V);
    cudaGetSymbolAddress((void**)&pX, g_X);

    const int Mq = BB * SDEC;   // 4096
    const int Mk = BB * SENC;   // 8192

    // Projections
    sgemm_bias_kernel<<<dim3(DIM / GBN, Mq / GBM), 256>>>(dec, q_w, q_b, pQ, Mq, DIM, DIM);
    sgemm_bias_kernel<<<dim3(DIM / GBN, Mk / GBM), 256>>>(enc, k_w, k_b, pK, Mk, DIM, DIM);
    sgemm_bias_kernel<<<dim3(DIM / GBN, Mk / GBM), 256>>>(enc, v_w, v_b, pV, Mk, DIM, DIM);

    // Attention
    cudaFuncSetAttribute(attn_kernel, cudaFuncAttributeMaxDynamicSharedMemorySize, ATTN_SMEM);
    attn_kernel<<<dim3(SDEC / BQ, NH, BB), 256, ATTN_SMEM>>>(enc_mask, pX);

    // Output projection
    sgemm_bias_kernel<<<dim3(DIM / GBN, Mq / GBM), 256>>>(pX, o_w, o_b, out, Mq, DIM, DIM);
}

// round 4
// speedup vs baseline: 1.3915x; 1.3915x over previous
#include <cuda_runtime.h>
#include <cuda_bf16.h>
#include <cstdint>
#include <math.h>

// Problem constants
#define BB     4
#define SENC   2048
#define SDEC   1024
#define DIM    1024
#define NH     16
#define HD     64
#define SCALE_INV (0.125f)

// Scratch
__device__ float g_Q[BB * SDEC * DIM];
__device__ float g_K[BB * SENC * DIM];
__device__ float g_V[BB * SENC * DIM];
__device__ float g_X[BB * SDEC * DIM];

// ============================ helpers ============================
__device__ __forceinline__ uint32_t pack_hi2(float x, float y) {
    __nv_bfloat16 a = __float2bfloat16_rn(x), b = __float2bfloat16_rn(y);
    return (uint32_t)__bfloat16_as_ushort(a) | ((uint32_t)__bfloat16_as_ushort(b) << 16);
}
__device__ __forceinline__ uint32_t pack_lo2(float x, float y) {
    __nv_bfloat16 a = __float2bfloat16_rn(x), b = __float2bfloat16_rn(y);
    __nv_bfloat16 la = __float2bfloat16_rn(x - __bfloat162float(a));
    __nv_bfloat16 lb = __float2bfloat16_rn(y - __bfloat162float(b));
    return (uint32_t)__bfloat16_as_ushort(la) | ((uint32_t)__bfloat16_as_ushort(lb) << 16);
}
__device__ __forceinline__ void mma_bf16(float* d, const uint32_t* a, const uint32_t* b) {
    asm volatile("mma.sync.aligned.m16n8k16.row.col.f32.bf16.bf16.f32 "
        "{%0,%1,%2,%3}, {%4,%5,%6,%7}, {%8,%9}, {%0,%1,%2,%3};"
        : "+f"(d[0]), "+f"(d[1]), "+f"(d[2]), "+f"(d[3])
        : "r"(a[0]), "r"(a[1]), "r"(a[2]), "r"(a[3]), "r"(b[0]), "r"(b[1]));
}

// ============================ HMMA GEMM ============================
// C[M,N] = A[M,K] @ W[K,N] + bias. fp32 I/O, bf16x2 3-pass split.
// Block 128x128, KB=32, 8 warps (2 x 4), warp tile 64x32.
#define ASTR 40   // A smem row stride (bf16 units)
#define BSTR 36   // B smem row stride

__global__ __launch_bounds__(256) void hgemm_bias(
    const float* __restrict__ A, const float* __restrict__ W,
    const float* __restrict__ bias, float* __restrict__ C,
    int M, int N, int K)
{
    __shared__ __align__(16) uint16_t As[2][128 * ASTR];   // [hi/lo][m][k]
    __shared__ __align__(16) uint16_t Bs[2][128 * BSTR];   // [hi/lo][n][k]

    const int t = threadIdx.x;
    const int lane = t & 31;
    const int wid  = t >> 5;
    const int g  = lane >> 2;   // 0..7
    const int tq = lane & 3;    // 0..3
    const int warp_m = wid & 1;       // 0..1
    const int warp_n = wid >> 1;      // 0..3
    const int bm = blockIdx.y * 128, bn = blockIdx.x * 128;

    float acc[4][4][4];
#pragma unroll
    for (int i = 0; i < 4; i++)
#pragma unroll
        for (int j = 0; j < 4; j++)
#pragma unroll
            for (int k = 0; k < 4; k++) acc[i][j][k] = 0.f;

    float4 av[4];
    float2 bv[4][2];

    // prefetch kb=0
#pragma unroll
    for (int it = 0; it < 4; it++) {
        int u = t + it * 256;
        int m = u >> 3, kq = (u & 7) * 4;
        av[it] = *(const float4*)(A + (size_t)(bm + m) * K + kq);
        int kp = u >> 6, n = (u & 63) * 2;
        const float* p = W + (size_t)(2 * kp) * N + bn + n;
        bv[it][0] = *(const float2*)p;
        bv[it][1] = *(const float2*)(p + N);
    }

    for (int kb = 0; kb < K; kb += 32) {
        // commit staged tile to smem (fp32 -> bf16 hi/lo)
#pragma unroll
        for (int it = 0; it < 4; it++) {
            int u = t + it * 256;
            int m = u >> 3, kq = (u & 7) * 4;
            float4 v = av[it];
            *(uint2*)&As[0][m * ASTR + kq] = make_uint2(pack_hi2(v.x, v.y), pack_hi2(v.z, v.w));
            *(uint2*)&As[1][m * ASTR + kq] = make_uint2(pack_lo2(v.x, v.y), pack_lo2(v.z, v.w));
            int kp = u >> 6, n = (u & 63) * 2;
            float2 r0 = bv[it][0], r1 = bv[it][1];
            *(uint32_t*)&Bs[0][n * BSTR + 2 * kp]       = pack_hi2(r0.x, r1.x);
            *(uint32_t*)&Bs[0][(n + 1) * BSTR + 2 * kp] = pack_hi2(r0.y, r1.y);
            *(uint32_t*)&Bs[1][n * BSTR + 2 * kp]       = pack_lo2(r0.x, r1.x);
            *(uint32_t*)&Bs[1][(n + 1) * BSTR + 2 * kp] = pack_lo2(r0.y, r1.y);
        }
        __syncthreads();

        // prefetch next kblock
        if (kb + 32 < K) {
#pragma unroll
            for (int it = 0; it < 4; it++) {
                int u = t + it * 256;
                int m = u >> 3, kq = (u & 7) * 4;
                av[it] = *(const float4*)(A + (size_t)(bm + m) * K + kb + 32 + kq);
                int kp = u >> 6, n = (u & 63) * 2;
                const float* p = W + (size_t)(kb + 32 + 2 * kp) * N + bn + n;
                bv[it][0] = *(const float2*)p;
                bv[it][1] = *(const float2*)(p + N);
            }
        }

        // compute: 2 k16 steps
#pragma unroll
        for (int ks = 0; ks < 2; ks++) {
            uint32_t ah[4][4], al[4][4], bh[4][2], bl[4][2];
#pragma unroll
            for (int mi = 0; mi < 4; mi++) {
                int r = (warp_m * 64 + mi * 16 + g) * ASTR + ks * 16 + 2 * tq;
                ah[mi][0] = *(const uint32_t*)&As[0][r];
                ah[mi][1] = *(const uint32_t*)&As[0][r + 8 * ASTR];
                ah[mi][2] = *(const uint32_t*)&As[0][r + 8];
                ah[mi][3] = *(const uint32_t*)&As[0][r + 8 * ASTR + 8];
                al[mi][0] = *(const uint32_t*)&As[1][r];
                al[mi][1] = *(const uint32_t*)&As[1][r + 8 * ASTR];
                al[mi][2] = *(const uint32_t*)&As[1][r + 8];
                al[mi][3] = *(const uint32_t*)&As[1][r + 8 * ASTR + 8];
            }
#pragma unroll
            for (int ni = 0; ni < 4; ni++) {
                int r = (warp_n * 32 + ni * 8 + g) * BSTR + ks * 16 + 2 * tq;
                bh[ni][0] = *(const uint32_t*)&Bs[0][r];
                bh[ni][1] = *(const uint32_t*)&Bs[0][r + 8];
                bl[ni][0] = *(const uint32_t*)&Bs[1][r];
                bl[ni][1] = *(const uint32_t*)&Bs[1][r + 8];
            }
#pragma unroll
            for (int mi = 0; mi < 4; mi++)
#pragma unroll
                for (int ni = 0; ni < 4; ni++) {
                    mma_bf16(acc[mi][ni], ah[mi], bh[ni]);
                    mma_bf16(acc[mi][ni], ah[mi], bl[ni]);
                    mma_bf16(acc[mi][ni], al[mi], bh[ni]);
                }
        }
        __syncthreads();
    }

    // epilogue: bias + store
#pragma unroll
    for (int mi = 0; mi < 4; mi++) {
        int r0 = bm + warp_m * 64 + mi * 16 + g;
#pragma unroll
        for (int ni = 0; ni < 4; ni++) {
            int c = bn + warp_n * 32 + ni * 8 + 2 * tq;
            float2 bb = *(const float2*)(bias + c);
            float* d = acc[mi][ni];
            *(float2*)(C + (size_t)r0 * N + c)       = make_float2(d[0] + bb.x, d[1] + bb.y);
            *(float2*)(C + (size_t)(r0 + 8) * N + c) = make_float2(d[2] + bb.x, d[3] + bb.y);
        }
    }
}

// ============================ Flash attention (fp32) ============================
#define BQ  64
#define BKT 64
#define PAD 68
#define ATTN_SMEM (4 * BQ * PAD * (int)sizeof(float))

__global__ __launch_bounds__(256) void attn_kernel(
    const unsigned int* __restrict__ mask, float* __restrict__ X)
{
    extern __shared__ float smf[];
    float* Qs = smf;
    float* Ks = smf + BQ * PAD;
    float* Vs = smf + 2 * BQ * PAD;
    float* Ps = smf + 3 * BQ * PAD;

    const int qt = blockIdx.x, h = blockIdx.y, b = blockIdx.z;
    const int t = threadIdx.x;
    const int tr = t / 16, tc = t % 16;
    const int q0 = qt * BQ;

    const float* Qg = g_Q + ((size_t)(b * SDEC + q0)) * DIM + h * HD;
    const float* Kg = g_K + ((size_t)b * SENC) * DIM + h * HD;
    const float* Vg = g_V + ((size_t)b * SENC) * DIM + h * HD;
    const unsigned int* mk = mask + (size_t)b * SENC;

#pragma unroll
    for (int it = 0; it < 4; it++) {
        int idx = (t + it * 256) * 4;
        int r = idx >> 6, d = idx & 63;
        float4 v = *(const float4*)(Qg + (size_t)r * DIM + d);
        Qs[(d + 0) * PAD + r] = v.x;
        Qs[(d + 1) * PAD + r] = v.y;
        Qs[(d + 2) * PAD + r] = v.z;
        Qs[(d + 3) * PAD + r] = v.w;
    }

    float m[4], l[4], o[4][4];
#pragma unroll
    for (int i = 0; i < 4; i++) {
        m[i] = -1e30f; l[i] = 0.f;
#pragma unroll
        for (int j = 0; j < 4; j++) o[i][j] = 0.f;
    }

    for (int k0 = 0; k0 < SENC; k0 += BKT) {
        __syncthreads();
#pragma unroll
        for (int it = 0; it < 4; it++) {
            int idx = (t + it * 256) * 4;
            int c = idx >> 6, d = idx & 63;
            float4 kv = *(const float4*)(Kg + (size_t)(k0 + c) * DIM + d);
            Ks[(d + 0) * PAD + c] = kv.x;
            Ks[(d + 1) * PAD + c] = kv.y;
            Ks[(d + 2) * PAD + c] = kv.z;
            Ks[(d + 3) * PAD + c] = kv.w;
            float4 vv = *(const float4*)(Vg + (size_t)(k0 + c) * DIM + d);
            *(float4*)&Vs[c * PAD + d] = vv;
        }
        __syncthreads();

        float s[4][4];
#pragma unroll
        for (int i = 0; i < 4; i++)
#pragma unroll
            for (int j = 0; j < 4; j++) s[i][j] = 0.f;
#pragma unroll
        for (int d = 0; d < HD; d++) {
            float ra[4];
#pragma unroll
            for (int i = 0; i < 4; i++) ra[i] = Qs[d * PAD + tr * 4 + i];
            float4 kb = *(const float4*)&Ks[d * PAD + tc * 4];
#pragma unroll
            for (int i = 0; i < 4; i++) {
                s[i][0] += ra[i] * kb.x;
                s[i][1] += ra[i] * kb.y;
                s[i][2] += ra[i] * kb.z;
                s[i][3] += ra[i] * kb.w;
            }
        }
#pragma unroll
        for (int j = 0; j < 4; j++) {
            bool msk = (mk[k0 + tc * 4 + j] != 0u);
#pragma unroll
            for (int i = 0; i < 4; i++)
                s[i][j] = msk ? -1e30f : s[i][j] * SCALE_INV;
        }
#pragma unroll
        for (int i = 0; i < 4; i++) {
            float v = fmaxf(fmaxf(s[i][0], s[i][1]), fmaxf(s[i][2], s[i][3]));
#pragma unroll
            for (int off = 1; off < 16; off <<= 1)
                v = fmaxf(v, __shfl_xor_sync(0xffffffffu, v, off));
            float mnew = fmaxf(m[i], v);
            float alpha = __expf(m[i] - mnew);
            float rs = 0.f;
#pragma unroll
            for (int j = 0; j < 4; j++) {
                float p = __expf(s[i][j] - mnew);
                s[i][j] = p;
                rs += p;
            }
#pragma unroll
            for (int off = 1; off < 16; off <<= 1)
                rs += __shfl_xor_sync(0xffffffffu, rs, off);
            l[i] = l[i] * alpha + rs;
            m[i] = mnew;
#pragma unroll
            for (int j = 0; j < 4; j++) o[i][j] *= alpha;
        }
#pragma unroll
        for (int i = 0; i < 4; i++)
            *(float4*)&Ps[(tr * 4 + i) * PAD + tc * 4] =
                make_float4(s[i][0], s[i][1], s[i][2], s[i][3]);
        __syncthreads();
#pragma unroll 8
        for (int c = 0; c < BKT; c++) {
            float4 v4 = *(const float4*)&Vs[c * PAD + tc * 4];
            float rp[4];
#pragma unroll
            for (int i = 0; i < 4; i++) rp[i] = Ps[(tr * 4 + i) * PAD + c];
#pragma unroll
            for (int i = 0; i < 4; i++) {
                o[i][0] += rp[i] * v4.x;
                o[i][1] += rp[i] * v4.y;
                o[i][2] += rp[i] * v4.z;
                o[i][3] += rp[i] * v4.w;
            }
        }
    }
#pragma unroll
    for (int i = 0; i < 4; i++) {
        int r = tr * 4 + i;
        float inv = 1.0f / l[i];
        *(float4*)&X[((size_t)(b * SDEC + q0 + r)) * DIM + h * HD + tc * 4] =
            make_float4(o[i][0] * inv, o[i][1] * inv, o[i][2] * inv, o[i][3] * inv);
    }
}

// ============================ Launch ============================
extern "C" void kernel_launch(void* const* d_in, const int* in_sizes, int n_in,
                              void* d_out, int out_size)
{
    const float*        enc      = (const float*)d_in[0];
    const unsigned int* enc_mask = (const unsigned int*)d_in[1];
    const float*        dec      = (const float*)d_in[2];
    const float*        q_w      = (const float*)d_in[3];
    const float*        q_b      = (const float*)d_in[4];
    const float*        k_w      = (const float*)d_in[5];
    const float*        k_b      = (const float*)d_in[6];
    const float*        v_w      = (const float*)d_in[7];
    const float*        v_b      = (const float*)d_in[8];
    const float*        o_w      = (const float*)d_in[9];
    const float*        o_b      = (const float*)d_in[10];
    float*              out      = (float*)d_out;

    float *pQ, *pK, *pV, *pX;
    cudaGetSymbolAddress((void**)&pQ, g_Q);
    cudaGetSymbolAddress((void**)&pK, g_K);
    cudaGetSymbolAddress((void**)&pV, g_V);
    cudaGetSymbolAddress((void**)&pX, g_X);

    const int Mq = BB * SDEC;   // 4096
    const int Mk = BB * SENC;   // 8192

    cudaFuncSetAttribute(attn_kernel, cudaFuncAttributeMaxDynamicSharedMemorySize, ATTN_SMEM);

    hgemm_bias<<<dim3(DIM / 128, Mq / 128), 256>>>(dec, q_w, q_b, pQ, Mq, DIM, DIM);
    hgemm_bias<<<dim3(DIM / 128, Mk / 128), 256>>>(enc, k_w, k_b, pK, Mk, DIM, DIM);
    hgemm_bias<<<dim3(DIM / 128, Mk / 128), 256>>>(enc, v_w, v_b, pV, Mk, DIM, DIM);

    attn_kernel<<<dim3(SDEC / BQ, NH, BB), 256, ATTN_SMEM>>>(enc_mask, pX);

    hgemm_bias<<<dim3(DIM / 128, Mq / 128), 256>>>(pX, o_w, o_b, out, Mq, DIM, DIM);
}

// round 5
// speedup vs baseline: 1.9184x; 1.3787x over previous
#include <cuda_runtime.h>
#include <cuda_bf16.h>
#include <cstdint>
#include <math.h>

// Problem constants
#define BB     4
#define SENC   2048
#define SDEC   1024
#define DIM    1024
#define NH     16
#define HD     64
// fold (1/sqrt(64)) * log2(e) into Q so softmax works in base-2 units
#define CS     (0.125f * 1.44269504088896f)

// Scratch
__device__ float g_Q[BB * SDEC * DIM];
__device__ float g_K[BB * SENC * DIM];
__device__ float g_V[BB * SENC * DIM];
__device__ float g_X[BB * SDEC * DIM];

// ============================ helpers ============================
__device__ __forceinline__ uint32_t smem_u32(const void* p) {
    uint32_t a;
    asm("{ .reg .u64 t; cvta.to.shared.u64 t, %1; cvt.u32.u64 %0, t; }" : "=r"(a) : "l"(p));
    return a;
}
__device__ __forceinline__ uint32_t pack_hi2(float x, float y) {
    __nv_bfloat16 a = __float2bfloat16_rn(x), b = __float2bfloat16_rn(y);
    return (uint32_t)__bfloat16_as_ushort(a) | ((uint32_t)__bfloat16_as_ushort(b) << 16);
}
__device__ __forceinline__ uint32_t pack_lo2(float x, float y) {
    __nv_bfloat16 a = __float2bfloat16_rn(x), b = __float2bfloat16_rn(y);
    __nv_bfloat16 la = __float2bfloat16_rn(x - __bfloat162float(a));
    __nv_bfloat16 lb = __float2bfloat16_rn(y - __bfloat162float(b));
    return (uint32_t)__bfloat16_as_ushort(la) | ((uint32_t)__bfloat16_as_ushort(lb) << 16);
}
__device__ __forceinline__ void mma_bf16(float* d, const uint32_t* a, const uint32_t* b) {
    asm volatile("mma.sync.aligned.m16n8k16.row.col.f32.bf16.bf16.f32 "
        "{%0,%1,%2,%3}, {%4,%5,%6,%7}, {%8,%9}, {%0,%1,%2,%3};"
        : "+f"(d[0]), "+f"(d[1]), "+f"(d[2]), "+f"(d[3])
        : "r"(a[0]), "r"(a[1]), "r"(a[2]), "r"(a[3]), "r"(b[0]), "r"(b[1]));
}
// exp2 on FMA/ALU pipes (no MUFU). u <= 0. ~3e-6 abs err.
__device__ __forceinline__ float exp2p(float u) {
    u = fmaxf(u, -60.0f);
    float n = rintf(u);
    float f = u - n;
    float p = 0.0013333558f;
    p = fmaf(p, f, 0.0096181291f);
    p = fmaf(p, f, 0.0555041087f);
    p = fmaf(p, f, 0.2402265070f);
    p = fmaf(p, f, 0.6931471806f);
    p = fmaf(p, f, 1.0f);
    int sb = (__float2int_rn(n) + 127) << 23;
    return p * __int_as_float(sb);
}
#define CP16(dst, src) \
    asm volatile("cp.async.cg.shared.global [%0], [%1], 16;" :: "r"(dst), "l"(src) : "memory")
#define CP_COMMIT() asm volatile("cp.async.commit_group;" ::: "memory")
#define CP_WAIT1()  asm volatile("cp.async.wait_group 1;" ::: "memory")

// ============================ HMMA GEMM (unchanged from R4) ============================
#define ASTR 40
#define BSTR 36

__global__ __launch_bounds__(256) void hgemm_bias(
    const float* __restrict__ A, const float* __restrict__ W,
    const float* __restrict__ bias, float* __restrict__ C,
    int M, int N, int K)
{
    __shared__ __align__(16) uint16_t As[2][128 * ASTR];
    __shared__ __align__(16) uint16_t Bs[2][128 * BSTR];

    const int t = threadIdx.x;
    const int lane = t & 31;
    const int wid  = t >> 5;
    const int g  = lane >> 2;
    const int tq = lane & 3;
    const int warp_m = wid & 1;
    const int warp_n = wid >> 1;
    const int bm = blockIdx.y * 128, bn = blockIdx.x * 128;

    float acc[4][4][4];
#pragma unroll
    for (int i = 0; i < 4; i++)
#pragma unroll
        for (int j = 0; j < 4; j++)
#pragma unroll
            for (int k = 0; k < 4; k++) acc[i][j][k] = 0.f;

    float4 av[4];
    float2 bv[4][2];
#pragma unroll
    for (int it = 0; it < 4; it++) {
        int u = t + it * 256;
        int m = u >> 3, kq = (u & 7) * 4;
        av[it] = *(const float4*)(A + (size_t)(bm + m) * K + kq);
        int kp = u >> 6, n = (u & 63) * 2;
        const float* p = W + (size_t)(2 * kp) * N + bn + n;
        bv[it][0] = *(const float2*)p;
        bv[it][1] = *(const float2*)(p + N);
    }

    for (int kb = 0; kb < K; kb += 32) {
#pragma unroll
        for (int it = 0; it < 4; it++) {
            int u = t + it * 256;
            int m = u >> 3, kq = (u & 7) * 4;
            float4 v = av[it];
            *(uint2*)&As[0][m * ASTR + kq] = make_uint2(pack_hi2(v.x, v.y), pack_hi2(v.z, v.w));
            *(uint2*)&As[1][m * ASTR + kq] = make_uint2(pack_lo2(v.x, v.y), pack_lo2(v.z, v.w));
            int kp = u >> 6, n = (u & 63) * 2;
            float2 r0 = bv[it][0], r1 = bv[it][1];
            *(uint32_t*)&Bs[0][n * BSTR + 2 * kp]       = pack_hi2(r0.x, r1.x);
            *(uint32_t*)&Bs[0][(n + 1) * BSTR + 2 * kp] = pack_hi2(r0.y, r1.y);
            *(uint32_t*)&Bs[1][n * BSTR + 2 * kp]       = pack_lo2(r0.x, r1.x);
            *(uint32_t*)&Bs[1][(n + 1) * BSTR + 2 * kp] = pack_lo2(r0.y, r1.y);
        }
        __syncthreads();

        if (kb + 32 < K) {
#pragma unroll
            for (int it = 0; it < 4; it++) {
                int u = t + it * 256;
                int m = u >> 3, kq = (u & 7) * 4;
                av[it] = *(const float4*)(A + (size_t)(bm + m) * K + kb + 32 + kq);
                int kp = u >> 6, n = (u & 63) * 2;
                const float* p = W + (size_t)(kb + 32 + 2 * kp) * N + bn + n;
                bv[it][0] = *(const float2*)p;
                bv[it][1] = *(const float2*)(p + N);
            }
        }

#pragma unroll
        for (int ks = 0; ks < 2; ks++) {
            uint32_t ah[4][4], al[4][4], bh[4][2], bl[4][2];
#pragma unroll
            for (int mi = 0; mi < 4; mi++) {
                int r = (warp_m * 64 + mi * 16 + g) * ASTR + ks * 16 + 2 * tq;
                ah[mi][0] = *(const uint32_t*)&As[0][r];
                ah[mi][1] = *(const uint32_t*)&As[0][r + 8 * ASTR];
                ah[mi][2] = *(const uint32_t*)&As[0][r + 8];
                ah[mi][3] = *(const uint32_t*)&As[0][r + 8 * ASTR + 8];
                al[mi][0] = *(const uint32_t*)&As[1][r];
                al[mi][1] = *(const uint32_t*)&As[1][r + 8 * ASTR];
                al[mi][2] = *(const uint32_t*)&As[1][r + 8];
                al[mi][3] = *(const uint32_t*)&As[1][r + 8 * ASTR + 8];
            }
#pragma unroll
            for (int ni = 0; ni < 4; ni++) {
                int r = (warp_n * 32 + ni * 8 + g) * BSTR + ks * 16 + 2 * tq;
                bh[ni][0] = *(const uint32_t*)&Bs[0][r];
                bh[ni][1] = *(const uint32_t*)&Bs[0][r + 8];
                bl[ni][0] = *(const uint32_t*)&Bs[1][r];
                bl[ni][1] = *(const uint32_t*)&Bs[1][r + 8];
            }
#pragma unroll
            for (int mi = 0; mi < 4; mi++)
#pragma unroll
                for (int ni = 0; ni < 4; ni++) {
                    mma_bf16(acc[mi][ni], ah[mi], bh[ni]);
                    mma_bf16(acc[mi][ni], ah[mi], bl[ni]);
                    mma_bf16(acc[mi][ni], al[mi], bh[ni]);
                }
        }
        __syncthreads();
    }

#pragma unroll
    for (int mi = 0; mi < 4; mi++) {
        int r0 = bm + warp_m * 64 + mi * 16 + g;
#pragma unroll
        for (int ni = 0; ni < 4; ni++) {
            int c = bn + warp_n * 32 + ni * 8 + 2 * tq;
            float2 bb = *(const float2*)(bias + c);
            float* d = acc[mi][ni];
            *(float2*)(C + (size_t)r0 * N + c)       = make_float2(d[0] + bb.x, d[1] + bb.y);
            *(float2*)(C + (size_t)(r0 + 8) * N + c) = make_float2(d[2] + bb.x, d[3] + bb.y);
        }
    }
}

// ============================ FA2 attention on mma.sync ============================
// BQ=128 q rows/block (8 warps x 16 rows), BK=64 keys/iter, HD=64.
// smem: double-buffered fp32 stages (cp.async) + bf16 hi/lo tiles.
#define STG_PAIR 33792                 // K stage 16384 + V stage 17408
#define OKH (2 * STG_PAIR)             // 67584
#define OKL (OKH + 9216)
#define OVH (OKL + 9216)
#define OVL (OVH + 9216)
#define ATTN_SMEM2 (OVL + 9216)        // 104448 B

__global__ __launch_bounds__(256, 1) void attn_mma(
    const unsigned int* __restrict__ mask, float* __restrict__ X)
{
    extern __shared__ char sm[];
    const uint32_t sb = smem_u32(sm);
    const int t = threadIdx.x, w = t >> 5, lane = t & 31;
    const int g = lane >> 2, tq = lane & 3;
    const int qt = blockIdx.x, h = blockIdx.y, b = blockIdx.z;
    const int q0 = qt * 128;

    const float* Qg = g_Q + ((size_t)(b * SDEC + q0 + 16 * w)) * DIM + h * HD;
    const float* Kg = g_K + ((size_t)(b * SENC)) * DIM + h * HD;
    const float* Vg = g_V + ((size_t)(b * SENC)) * DIM + h * HD;
    const unsigned int* mk = mask + (size_t)b * SENC;

    // Q fragments (scaled by CS, bf16 hi/lo) for 4 k16 chunks
    uint32_t qh[4][4], ql[4][4];
#pragma unroll
    for (int ks = 0; ks < 4; ks++) {
        float2 a0 = *(const float2*)(Qg + (size_t)g * DIM + ks * 16 + 2 * tq);
        float2 a1 = *(const float2*)(Qg + (size_t)(g + 8) * DIM + ks * 16 + 2 * tq);
        float2 a2 = *(const float2*)(Qg + (size_t)g * DIM + ks * 16 + 8 + 2 * tq);
        float2 a3 = *(const float2*)(Qg + (size_t)(g + 8) * DIM + ks * 16 + 8 + 2 * tq);
        float x0 = a0.x * CS, y0 = a0.y * CS, x1 = a1.x * CS, y1 = a1.y * CS;
        float x2 = a2.x * CS, y2 = a2.y * CS, x3 = a3.x * CS, y3 = a3.y * CS;
        qh[ks][0] = pack_hi2(x0, y0); ql[ks][0] = pack_lo2(x0, y0);
        qh[ks][1] = pack_hi2(x1, y1); ql[ks][1] = pack_lo2(x1, y1);
        qh[ks][2] = pack_hi2(x2, y2); ql[ks][2] = pack_lo2(x2, y2);
        qh[ks][3] = pack_hi2(x3, y3); ql[ks][3] = pack_lo2(x3, y3);
    }

    float m0 = -1e30f, m1 = -1e30f, l0 = 0.f, l1 = 0.f;
    float oacc[8][4];
#pragma unroll
    for (int ni = 0; ni < 8; ni++)
#pragma unroll
        for (int k = 0; k < 4; k++) oacc[ni][k] = 0.f;

    auto issue = [&](int kb, int st) {
        uint32_t dk = sb + st * STG_PAIR;
        uint32_t dv = dk + 16384;
#pragma unroll
        for (int c = 0; c < 4; c++) {
            int cI = t + c * 256;
            int key = cI >> 4, off = (cI & 15) * 4;
            CP16(dk + (uint32_t)(key * 256 + off * 4), Kg + (size_t)(kb + key) * DIM + off);
            CP16(dv + (uint32_t)(key * 272 + off * 4), Vg + (size_t)(kb + key) * DIM + off);
        }
    };

    issue(0, 0);
    CP_COMMIT();

    const uint32_t* KhU = (const uint32_t*)(sm + OKH);
    const uint32_t* KlU = (const uint32_t*)(sm + OKL);
    const uint32_t* VhU = (const uint32_t*)(sm + OVH);
    const uint32_t* VlU = (const uint32_t*)(sm + OVL);

    for (int i = 0; i < SENC / 64; i++) {
        const int k0 = i * 64;
        const int st = i & 1;

        if (i + 1 < SENC / 64) issue((i + 1) * 64, (i + 1) & 1);
        CP_COMMIT();
        CP_WAIT1();
        __syncthreads();

        // convert fp32 stage -> bf16 hi/lo tiles
        {
            const char* stK = sm + st * STG_PAIR;
            const char* stV = stK + 16384;
#pragma unroll
            for (int it = 0; it < 4; it++) {
                int idx = t + it * 256;
                int key = idx >> 4, d = (idx & 15) * 4;
                float4 v = *(const float4*)(stK + key * 256 + d * 4);
                *(uint2*)(sm + OKH + (key * 72 + d) * 2) =
                    make_uint2(pack_hi2(v.x, v.y), pack_hi2(v.z, v.w));
                *(uint2*)(sm + OKL + (key * 72 + d) * 2) =
                    make_uint2(pack_lo2(v.x, v.y), pack_lo2(v.z, v.w));
            }
#pragma unroll
            for (int it = 0; it < 2; it++) {
                int item = t + it * 256;
                int key0 = (item & 31) * 2, d4 = ((item >> 5) & 15) * 4;
                float4 a = *(const float4*)(stV + key0 * 272 + d4 * 4);
                float4 c = *(const float4*)(stV + (key0 + 1) * 272 + d4 * 4);
                float av[4] = {a.x, a.y, a.z, a.w};
                float cv[4] = {c.x, c.y, c.z, c.w};
#pragma unroll
                for (int j = 0; j < 4; j++) {
                    *(uint32_t*)(sm + OVH + ((d4 + j) * 72 + key0) * 2) = pack_hi2(av[j], cv[j]);
                    *(uint32_t*)(sm + OVL + ((d4 + j) * 72 + key0) * 2) = pack_lo2(av[j], cv[j]);
                }
            }
        }
        __syncthreads();

        // S = Q @ K^T (3-pass bf16x2), output in base-2 logit units
        float sacc[8][4];
#pragma unroll
        for (int ni = 0; ni < 8; ni++)
#pragma unroll
            for (int k = 0; k < 4; k++) sacc[ni][k] = 0.f;
#pragma unroll
        for (int ks = 0; ks < 4; ks++) {
#pragma unroll
            for (int ni = 0; ni < 8; ni++) {
                int base = (8 * ni + g) * 36 + ks * 8 + tq;
                uint32_t bh[2], bl[2];
                bh[0] = KhU[base]; bh[1] = KhU[base + 4];
                bl[0] = KlU[base]; bl[1] = KlU[base + 4];
                mma_bf16(sacc[ni], qh[ks], bh);
                mma_bf16(sacc[ni], ql[ks], bh);
                mma_bf16(sacc[ni], qh[ks], bl);
            }
        }

        // mask
#pragma unroll
        for (int ni = 0; ni < 8; ni++) {
            uint2 mw = *(const uint2*)(mk + k0 + 8 * ni + 2 * tq);
            if (mw.x) { sacc[ni][0] = -1e30f; sacc[ni][2] = -1e30f; }
            if (mw.y) { sacc[ni][1] = -1e30f; sacc[ni][3] = -1e30f; }
        }

        // online softmax (rows g, g+8); reduce over the 4 tq lanes
        float v0 = -1e30f, v1 = -1e30f;
#pragma unroll
        for (int ni = 0; ni < 8; ni++) {
            v0 = fmaxf(v0, fmaxf(sacc[ni][0], sacc[ni][1]));
            v1 = fmaxf(v1, fmaxf(sacc[ni][2], sacc[ni][3]));
        }
        v0 = fmaxf(v0, __shfl_xor_sync(0xffffffffu, v0, 1));
        v0 = fmaxf(v0, __shfl_xor_sync(0xffffffffu, v0, 2));
        v1 = fmaxf(v1, __shfl_xor_sync(0xffffffffu, v1, 1));
        v1 = fmaxf(v1, __shfl_xor_sync(0xffffffffu, v1, 2));
        float mn0 = fmaxf(m0, v0), mn1 = fmaxf(m1, v1);
        float al0 = exp2p(m0 - mn0), al1 = exp2p(m1 - mn1);
        m0 = mn0; m1 = mn1;

        float rs0 = 0.f, rs1 = 0.f;
#pragma unroll
        for (int ni = 0; ni < 8; ni++) {
            sacc[ni][0] = exp2p(sacc[ni][0] - mn0); rs0 += sacc[ni][0];
            sacc[ni][1] = exp2p(sacc[ni][1] - mn0); rs0 += sacc[ni][1];
            sacc[ni][2] = exp2p(sacc[ni][2] - mn1); rs1 += sacc[ni][2];
            sacc[ni][3] = exp2p(sacc[ni][3] - mn1); rs1 += sacc[ni][3];
        }
        rs0 += __shfl_xor_sync(0xffffffffu, rs0, 1);
        rs0 += __shfl_xor_sync(0xffffffffu, rs0, 2);
        rs1 += __shfl_xor_sync(0xffffffffu, rs1, 1);
        rs1 += __shfl_xor_sync(0xffffffffu, rs1, 2);
        l0 = l0 * al0 + rs0;
        l1 = l1 * al1 + rs1;
#pragma unroll
        for (int ni = 0; ni < 8; ni++) {
            oacc[ni][0] *= al0; oacc[ni][1] *= al0;
            oacc[ni][2] *= al1; oacc[ni][3] *= al1;
        }

        // P fragments (hi/lo) straight from registers
        uint32_t pah[4][4], pal[4][4];
#pragma unroll
        for (int j = 0; j < 4; j++) {
            pah[j][0] = pack_hi2(sacc[2 * j][0], sacc[2 * j][1]);
            pal[j][0] = pack_lo2(sacc[2 * j][0], sacc[2 * j][1]);
            pah[j][1] = pack_hi2(sacc[2 * j][2], sacc[2 * j][3]);
            pal[j][1] = pack_lo2(sacc[2 * j][2], sacc[2 * j][3]);
            pah[j][2] = pack_hi2(sacc[2 * j + 1][0], sacc[2 * j + 1][1]);
            pal[j][2] = pack_lo2(sacc[2 * j + 1][0], sacc[2 * j + 1][1]);
            pah[j][3] = pack_hi2(sacc[2 * j + 1][2], sacc[2 * j + 1][3]);
            pal[j][3] = pack_lo2(sacc[2 * j + 1][2], sacc[2 * j + 1][3]);
        }

        // O += P @ V (3-pass)
#pragma unroll
        for (int j = 0; j < 4; j++) {
#pragma unroll
            for (int ni = 0; ni < 8; ni++) {
                int base = (8 * ni + g) * 36 + j * 8 + tq;
                uint32_t vh[2], vl[2];
                vh[0] = VhU[base]; vh[1] = VhU[base + 4];
                vl[0] = VlU[base]; vl[1] = VlU[base + 4];
                mma_bf16(oacc[ni], pah[j], vh);
                mma_bf16(oacc[ni], pal[j], vh);
                mma_bf16(oacc[ni], pah[j], vl);
            }
        }
        __syncthreads();
    }

    // normalize + write X[b, q, h*64 + d]
    float inv0 = 1.0f / l0, inv1 = 1.0f / l1;
    const size_t row0 = (size_t)(b * SDEC + q0 + 16 * w + g);
#pragma unroll
    for (int ni = 0; ni < 8; ni++) {
        int col = h * HD + 8 * ni + 2 * tq;
        *(float2*)(X + row0 * DIM + col) =
            make_float2(oacc[ni][0] * inv0, oacc[ni][1] * inv0);
        *(float2*)(X + (row0 + 8) * DIM + col) =
            make_float2(oacc[ni][2] * inv1, oacc[ni][3] * inv1);
    }
}

// ============================ Launch ============================
extern "C" void kernel_launch(void* const* d_in, const int* in_sizes, int n_in,
                              void* d_out, int out_size)
{
    const float*        enc      = (const float*)d_in[0];
    const unsigned int* enc_mask = (const unsigned int*)d_in[1];
    const float*        dec      = (const float*)d_in[2];
    const float*        q_w      = (const float*)d_in[3];
    const float*        q_b      = (const float*)d_in[4];
    const float*        k_w      = (const float*)d_in[5];
    const float*        k_b      = (const float*)d_in[6];
    const float*        v_w      = (const float*)d_in[7];
    const float*        v_b      = (const float*)d_in[8];
    const float*        o_w      = (const float*)d_in[9];
    const float*        o_b      = (const float*)d_in[10];
    float*              out      = (float*)d_out;

    float *pQ, *pK, *pV, *pX;
    cudaGetSymbolAddress((void**)&pQ, g_Q);
    cudaGetSymbolAddress((void**)&pK, g_K);
    cudaGetSymbolAddress((void**)&pV, g_V);
    cudaGetSymbolAddress((void**)&pX, g_X);

    const int Mq = BB * SDEC;   // 4096
    const int Mk = BB * SENC;   // 8192

    cudaFuncSetAttribute(attn_mma, cudaFuncAttributeMaxDynamicSharedMemorySize, ATTN_SMEM2);

    hgemm_bias<<<dim3(DIM / 128, Mq / 128), 256>>>(dec, q_w, q_b, pQ, Mq, DIM, DIM);
    hgemm_bias<<<dim3(DIM / 128, Mk / 128), 256>>>(enc, k_w, k_b, pK, Mk, DIM, DIM);
    hgemm_bias<<<dim3(DIM / 128, Mk / 128), 256>>>(enc, v_w, v_b, pV, Mk, DIM, DIM);

    attn_mma<<<dim3(SDEC / 128, NH, BB), 256, ATTN_SMEM2>>>(enc_mask, pX);

    hgemm_bias<<<dim3(DIM / 128, Mq / 128), 256>>>(pX, o_w, o_b, out, Mq, DIM, DIM);
}

// round 6
// speedup vs baseline: 2.4065x; 1.2544x over previous
#include <cuda_runtime.h>
#include <cuda_bf16.h>
#include <cstdint>

#define BB 4
#define SENC 2048
#define SDEC 1024
#define DIM 1024
#define NH 16
#define HD 64
#define CS (0.125f * 1.44269504088896f)   // 1/sqrt(64) * log2(e)

// ================= persistent packed-bf16 hi/lo scratch (uint32 = 2 bf16) ==
__device__ uint32_t g_dech[4096*512], g_decl[4096*512];
__device__ uint32_t g_ench[8192*512], g_encl[8192*512];
__device__ uint32_t g_wth[4][1024*512], g_wtl[4][1024*512];   // transposed [n][kpair]
__device__ uint32_t g_Qh[4096*512],  g_Ql[4096*512];          // CS pre-folded
__device__ uint32_t g_Kh[8192*512],  g_Kl[8192*512];
__device__ uint32_t g_Vh[8192*512],  g_Vl[8192*512];
__device__ uint32_t g_Xh[4096*512],  g_Xl[4096*512];

// ============================ helpers ============================
__device__ __forceinline__ uint32_t smem_u32(const void* p) {
    uint32_t a;
    asm("{ .reg .u64 t; cvta.to.shared.u64 t, %1; cvt.u32.u64 %0, t; }" : "=r"(a) : "l"(p));
    return a;
}
__device__ __forceinline__ uint32_t pack_hi2(float x, float y) {
    __nv_bfloat16 a = __float2bfloat16_rn(x), b = __float2bfloat16_rn(y);
    return (uint32_t)__bfloat16_as_ushort(a) | ((uint32_t)__bfloat16_as_ushort(b) << 16);
}
__device__ __forceinline__ uint32_t pack_lo2(float x, float y) {
    __nv_bfloat16 a = __float2bfloat16_rn(x), b = __float2bfloat16_rn(y);
    __nv_bfloat16 la = __float2bfloat16_rn(x - __bfloat162float(a));
    __nv_bfloat16 lb = __float2bfloat16_rn(y - __bfloat162float(b));
    return (uint32_t)__bfloat16_as_ushort(la) | ((uint32_t)__bfloat16_as_ushort(lb) << 16);
}
__device__ __forceinline__ void mma_bf16(float* d, const uint32_t* a, const uint32_t* b) {
    asm volatile("mma.sync.aligned.m16n8k16.row.col.f32.bf16.bf16.f32 "
        "{%0,%1,%2,%3}, {%4,%5,%6,%7}, {%8,%9}, {%0,%1,%2,%3};"
        : "+f"(d[0]), "+f"(d[1]), "+f"(d[2]), "+f"(d[3])
        : "r"(a[0]), "r"(a[1]), "r"(a[2]), "r"(a[3]), "r"(b[0]), "r"(b[1]));
}
__device__ __forceinline__ void ldmx4_trans(uint32_t* r, uint32_t addr) {
    asm volatile("ldmatrix.sync.aligned.m8n8.x4.trans.shared.b16 {%0,%1,%2,%3}, [%4];"
        : "=r"(r[0]), "=r"(r[1]), "=r"(r[2]), "=r"(r[3]) : "r"(addr));
}
// exp2 on FMA/ALU pipes. u <= 0.
__device__ __forceinline__ float exp2p(float u) {
    u = fmaxf(u, -60.0f);
    float n = rintf(u);
    float f = u - n;
    float p = 0.0013333558f;
    p = fmaf(p, f, 0.0096181291f);
    p = fmaf(p, f, 0.0555041087f);
    p = fmaf(p, f, 0.2402265070f);
    p = fmaf(p, f, 0.6931471806f);
    p = fmaf(p, f, 1.0f);
    int sb = (__float2int_rn(n) + 127) << 23;
    return p * __int_as_float(sb);
}
#define CP16(dst, src) \
    asm volatile("cp.async.cg.shared.global [%0], [%1], 16;" :: "r"(dst), "l"(src) : "memory")
#define CP_COMMIT() asm volatile("cp.async.commit_group;" ::: "memory")
#define CP_WAIT1()  asm volatile("cp.async.wait_group 1;" ::: "memory")

// ============================ convert kernels ============================
__global__ __launch_bounds__(256) void conv_act(
    const float* __restrict__ A, uint32_t* __restrict__ H, uint32_t* __restrict__ L)
{
    int i = blockIdx.x * 256 + threadIdx.x;
    float2 v = ((const float2*)A)[i];
    H[i] = pack_hi2(v.x, v.y);
    L[i] = pack_lo2(v.x, v.y);
}

// W[K=1024][N=1024] -> transposed packed [n][kpair] hi/lo
__global__ __launch_bounds__(256) void conv_wt(
    const float* __restrict__ W, uint32_t* __restrict__ Th, uint32_t* __restrict__ Tl)
{
    __shared__ float tile[64][33];
    int k0 = blockIdx.y * 64, n0 = blockIdx.x * 32;
    int tx = threadIdx.x & 31, ty = threadIdx.x >> 5;
    for (int r = ty; r < 64; r += 8)
        tile[r][tx] = W[(size_t)(k0 + r) * 1024 + n0 + tx];
    __syncthreads();
    for (int nn = ty; nn < 32; nn += 8) {
        float a = tile[2 * tx][nn], b = tile[2 * tx + 1][nn];
        Th[(size_t)(n0 + nn) * 512 + (k0 >> 1) + tx] = pack_hi2(a, b);
        Tl[(size_t)(n0 + nn) * 512 + (k0 >> 1) + tx] = pack_lo2(a, b);
    }
}

// ============================ HMMA GEMM (pre-packed operands) ============
// C[M,1024] = A[M,1024] @ W + bias. 3-pass bf16x2. Block 128x128, KB=32,
// cp.async double buffer. Epilogue: fp32 (Cf) or packed hi/lo * scale.
#define AST 20   // smem row stride in uint32 (16 data + 4 pad)

__global__ __launch_bounds__(256) void hgemm(
    const uint32_t* __restrict__ Ah, const uint32_t* __restrict__ Al,
    const uint32_t* __restrict__ Bth, const uint32_t* __restrict__ Btl,
    const float* __restrict__ bias,
    float* __restrict__ Cf, uint32_t* __restrict__ Ch, uint32_t* __restrict__ Cl,
    float scale)
{
    extern __shared__ uint32_t smu[];
    const uint32_t sb = smem_u32(smu);
    const int t = threadIdx.x, lane = t & 31, wid = t >> 5;
    const int g = lane >> 2, tq = lane & 3;
    const int wm = wid & 1, wn = wid >> 1;
    const int bm = blockIdx.y * 128, bn = blockIdx.x * 128;

    float acc[4][4][4];
#pragma unroll
    for (int i = 0; i < 4; i++)
#pragma unroll
        for (int j = 0; j < 4; j++)
#pragma unroll
            for (int k = 0; k < 4; k++) acc[i][j][k] = 0.f;

    auto issue = [&](int kb, int st) {
        const uint32_t base = sb + st * 40960;
        const int row = t >> 2, ch = t & 3;
#pragma unroll
        for (int c = 0; c < 8; c++) {
            int tile = c >> 1;                       // 0:Ah 1:Al 2:Bh 3:Bl
            int r = (c & 1) * 64 + row;
            const uint32_t* src = (tile == 0) ? Ah : (tile == 1) ? Al
                                : (tile == 2) ? Bth : Btl;
            int grow = ((tile < 2) ? bm : bn) + r;
            CP16(base + (uint32_t)(tile * 2560 + r * AST + ch * 4) * 4,
                 src + (size_t)grow * 512 + (kb >> 1) + ch * 4);
        }
    };

    issue(0, 0);
    CP_COMMIT();

    for (int i = 0; i < 32; i++) {
        int kb = i * 32;
        if (i + 1 < 32) issue(kb + 32, (i + 1) & 1);
        CP_COMMIT();
        CP_WAIT1();
        __syncthreads();

        const uint32_t* S   = smu + (i & 1) * 10240;
        const uint32_t* SAh = S;
        const uint32_t* SAl = S + 2560;
        const uint32_t* SBh = S + 5120;
        const uint32_t* SBl = S + 7680;

#pragma unroll
        for (int ks = 0; ks < 2; ks++) {
            uint32_t ah[4][4], al[4][4], bh[4][2], bl[4][2];
#pragma unroll
            for (int mi = 0; mi < 4; mi++) {
                int r = (wm * 64 + mi * 16 + g) * AST + ks * 8 + tq;
                ah[mi][0] = SAh[r];           al[mi][0] = SAl[r];
                ah[mi][1] = SAh[r + 8 * AST]; al[mi][1] = SAl[r + 8 * AST];
                ah[mi][2] = SAh[r + 4];       al[mi][2] = SAl[r + 4];
                ah[mi][3] = SAh[r + 8 * AST + 4]; al[mi][3] = SAl[r + 8 * AST + 4];
            }
#pragma unroll
            for (int ni = 0; ni < 4; ni++) {
                int r = (wn * 32 + ni * 8 + g) * AST + ks * 8 + tq;
                bh[ni][0] = SBh[r];     bh[ni][1] = SBh[r + 4];
                bl[ni][0] = SBl[r];     bl[ni][1] = SBl[r + 4];
            }
#pragma unroll
            for (int mi = 0; mi < 4; mi++)
#pragma unroll
                for (int ni = 0; ni < 4; ni++) {
                    mma_bf16(acc[mi][ni], ah[mi], bh[ni]);
                    mma_bf16(acc[mi][ni], ah[mi], bl[ni]);
                    mma_bf16(acc[mi][ni], al[mi], bh[ni]);
                }
        }
        __syncthreads();
    }

#pragma unroll
    for (int mi = 0; mi < 4; mi++) {
        int r0 = bm + wm * 64 + mi * 16 + g;
#pragma unroll
        for (int ni = 0; ni < 4; ni++) {
            int c = bn + wn * 32 + ni * 8 + 2 * tq;
            float2 bb = *(const float2*)(bias + c);
            float* d = acc[mi][ni];
            if (Cf) {
                *(float2*)(Cf + (size_t)r0 * 1024 + c) =
                    make_float2(d[0] + bb.x, d[1] + bb.y);
                *(float2*)(Cf + (size_t)(r0 + 8) * 1024 + c) =
                    make_float2(d[2] + bb.x, d[3] + bb.y);
            } else {
                float x0 = (d[0] + bb.x) * scale, y0 = (d[1] + bb.y) * scale;
                float x1 = (d[2] + bb.x) * scale, y1 = (d[3] + bb.y) * scale;
                size_t cp = (size_t)(c >> 1);
                Ch[(size_t)r0 * 512 + cp]       = pack_hi2(x0, y0);
                Cl[(size_t)r0 * 512 + cp]       = pack_lo2(x0, y0);
                Ch[(size_t)(r0 + 8) * 512 + cp] = pack_hi2(x1, y1);
                Cl[(size_t)(r0 + 8) * 512 + cp] = pack_lo2(x1, y1);
            }
        }
    }
}

// ============================ FA2 attention, pre-packed bf16 =============
// 128 q rows/block (8 warps), 64 keys/iter. Double-buffered bf16 K/V tiles
// (cp.async). K frags: manual LDS on [key][36u32] rows. V frags: ldmatrix.trans.
// Stage: Kh,Kl,Vh,Vl @ 9216B each = 36864B; 2 stages = 73728B.
#define ATTN_SMEM (2 * 36864)

__global__ __launch_bounds__(256, 1) void attn_mma(const unsigned int* __restrict__ mask)
{
    extern __shared__ uint32_t smu[];
    const uint32_t sb = smem_u32(smu);
    const int t = threadIdx.x, w = t >> 5, lane = t & 31;
    const int g = lane >> 2, tq = lane & 3;
    const int qt = blockIdx.x, h = blockIdx.y, b = blockIdx.z;
    const int q0 = qt * 128;
    const unsigned int* mk = mask + (size_t)b * SENC;

    // Q fragments direct from packed global (CS pre-folded)
    const size_t qrow = (size_t)(b * SDEC + q0 + 16 * w);
    uint32_t qh[4][4], ql[4][4];
#pragma unroll
    for (int ks = 0; ks < 4; ks++) {
        size_t p0 = (qrow + g) * 512 + h * 32 + ks * 8 + tq;
        size_t p1 = (qrow + g + 8) * 512 + h * 32 + ks * 8 + tq;
        qh[ks][0] = g_Qh[p0]; qh[ks][1] = g_Qh[p1];
        qh[ks][2] = g_Qh[p0 + 4]; qh[ks][3] = g_Qh[p1 + 4];
        ql[ks][0] = g_Ql[p0]; ql[ks][1] = g_Ql[p1];
        ql[ks][2] = g_Ql[p0 + 4]; ql[ks][3] = g_Ql[p1 + 4];
    }

    float m0 = -1e30f, m1 = -1e30f, l0 = 0.f, l1 = 0.f;
    float oacc[8][4];
#pragma unroll
    for (int ni = 0; ni < 8; ni++)
#pragma unroll
        for (int k = 0; k < 4; k++) oacc[ni][k] = 0.f;

    auto issue = [&](int kb, int st) {
        const uint32_t base = sb + st * 36864;
        const uint32_t* srcs[4] = {g_Kh, g_Kl, g_Vh, g_Vl};
        const int keyl = t >> 3, ch = t & 7;
#pragma unroll
        for (int c = 0; c < 8; c++) {
            int tile = c >> 1;
            int key = (c & 1) * 32 + keyl;
            CP16(base + (uint32_t)(tile * 9216 + key * 144 + ch * 16),
                 srcs[tile] + (size_t)(b * SENC + kb + key) * 512 + h * 32 + ch * 4);
        }
    };

    issue(0, 0);
    CP_COMMIT();

    for (int i = 0; i < SENC / 64; i++) {
        const int k0 = i * 64, st = i & 1;
        if (i + 1 < SENC / 64) issue((i + 1) * 64, (i + 1) & 1);
        CP_COMMIT();
        CP_WAIT1();
        __syncthreads();

        const uint32_t* SKh = smu + st * 9216;        // 36864B/4
        const uint32_t* SKl = SKh + 2304;
        const uint32_t vbase = sb + st * 36864 + 18432;  // Vh bytes; Vl at +9216

        // ---- S = Q K^T (3-pass) ----
        float sacc[8][4];
#pragma unroll
        for (int ni = 0; ni < 8; ni++)
#pragma unroll
            for (int k = 0; k < 4; k++) sacc[ni][k] = 0.f;
#pragma unroll
        for (int ks = 0; ks < 4; ks++) {
#pragma unroll
            for (int ni = 0; ni < 8; ni++) {
                int base = (8 * ni + g) * 36 + ks * 8 + tq;
                uint32_t bh[2], bl[2];
                bh[0] = SKh[base]; bh[1] = SKh[base + 4];
                bl[0] = SKl[base]; bl[1] = SKl[base + 4];
                mma_bf16(sacc[ni], qh[ks], bh);
                mma_bf16(sacc[ni], ql[ks], bh);
                mma_bf16(sacc[ni], qh[ks], bl);
            }
        }

        // ---- mask ----
#pragma unroll
        for (int ni = 0; ni < 8; ni++) {
            uint2 mw = *(const uint2*)(mk + k0 + 8 * ni + 2 * tq);
            if (mw.x) { sacc[ni][0] = -1e30f; sacc[ni][2] = -1e30f; }
            if (mw.y) { sacc[ni][1] = -1e30f; sacc[ni][3] = -1e30f; }
        }

        // ---- online softmax (base-2) ----
        float v0 = -1e30f, v1 = -1e30f;
#pragma unroll
        for (int ni = 0; ni < 8; ni++) {
            v0 = fmaxf(v0, fmaxf(sacc[ni][0], sacc[ni][1]));
            v1 = fmaxf(v1, fmaxf(sacc[ni][2], sacc[ni][3]));
        }
        v0 = fmaxf(v0, __shfl_xor_sync(0xffffffffu, v0, 1));
        v0 = fmaxf(v0, __shfl_xor_sync(0xffffffffu, v0, 2));
        v1 = fmaxf(v1, __shfl_xor_sync(0xffffffffu, v1, 1));
        v1 = fmaxf(v1, __shfl_xor_sync(0xffffffffu, v1, 2));
        float mn0 = fmaxf(m0, v0), mn1 = fmaxf(m1, v1);
        float al0 = exp2p(m0 - mn0), al1 = exp2p(m1 - mn1);
        m0 = mn0; m1 = mn1;

        float rs0 = 0.f, rs1 = 0.f;
#pragma unroll
        for (int ni = 0; ni < 8; ni++) {
            sacc[ni][0] = exp2p(sacc[ni][0] - mn0); rs0 += sacc[ni][0];
            sacc[ni][1] = exp2p(sacc[ni][1] - mn0); rs0 += sacc[ni][1];
            sacc[ni][2] = exp2p(sacc[ni][2] - mn1); rs1 += sacc[ni][2];
            sacc[ni][3] = exp2p(sacc[ni][3] - mn1); rs1 += sacc[ni][3];
        }
        rs0 += __shfl_xor_sync(0xffffffffu, rs0, 1);
        rs0 += __shfl_xor_sync(0xffffffffu, rs0, 2);
        rs1 += __shfl_xor_sync(0xffffffffu, rs1, 1);
        rs1 += __shfl_xor_sync(0xffffffffu, rs1, 2);
        l0 = l0 * al0 + rs0;
        l1 = l1 * al1 + rs1;
#pragma unroll
        for (int ni = 0; ni < 8; ni++) {
            oacc[ni][0] *= al0; oacc[ni][1] *= al0;
            oacc[ni][2] *= al1; oacc[ni][3] *= al1;
        }

        // ---- P fragments ----
        uint32_t pah[4][4], pal[4][4];
#pragma unroll
        for (int j = 0; j < 4; j++) {
            pah[j][0] = pack_hi2(sacc[2 * j][0], sacc[2 * j][1]);
            pal[j][0] = pack_lo2(sacc[2 * j][0], sacc[2 * j][1]);
            pah[j][1] = pack_hi2(sacc[2 * j][2], sacc[2 * j][3]);
            pal[j][1] = pack_lo2(sacc[2 * j][2], sacc[2 * j][3]);
            pah[j][2] = pack_hi2(sacc[2 * j + 1][0], sacc[2 * j + 1][1]);
            pal[j][2] = pack_lo2(sacc[2 * j + 1][0], sacc[2 * j + 1][1]);
            pah[j][3] = pack_hi2(sacc[2 * j + 1][2], sacc[2 * j + 1][3]);
            pal[j][3] = pack_lo2(sacc[2 * j + 1][2], sacc[2 * j + 1][3]);
        }

        // ---- O += P V (3-pass), V frags via ldmatrix.trans ----
#pragma unroll
        for (int j = 0; j < 4; j++) {
            uint32_t rowoff = (uint32_t)((16 * j + (lane & 15)) * 144);
#pragma unroll
            for (int n2 = 0; n2 < 8; n2 += 2) {
                uint32_t va = vbase + rowoff + n2 * 16 + ((lane >> 4) & 1) * 16;
                uint32_t vrh[4], vrl[4];
                ldmx4_trans(vrh, va);
                ldmx4_trans(vrl, va + 9216);
                mma_bf16(oacc[n2],     pah[j], &vrh[0]);
                mma_bf16(oacc[n2],     pal[j], &vrh[0]);
                mma_bf16(oacc[n2],     pah[j], &vrl[0]);
                mma_bf16(oacc[n2 + 1], pah[j], &vrh[2]);
                mma_bf16(oacc[n2 + 1], pal[j], &vrh[2]);
                mma_bf16(oacc[n2 + 1], pah[j], &vrl[2]);
            }
        }
        __syncthreads();
    }

    // ---- normalize + write packed X ----
    float inv0 = 1.0f / l0, inv1 = 1.0f / l1;
    const size_t row0 = qrow + g;
#pragma unroll
    for (int ni = 0; ni < 8; ni++) {
        size_t cp = (size_t)(h * 32 + ni * 4 + tq);
        float x0 = oacc[ni][0] * inv0, y0 = oacc[ni][1] * inv0;
        float x1 = oacc[ni][2] * inv1, y1 = oacc[ni][3] * inv1;
        g_Xh[row0 * 512 + cp]       = pack_hi2(x0, y0);
        g_Xl[row0 * 512 + cp]       = pack_lo2(x0, y0);
        g_Xh[(row0 + 8) * 512 + cp] = pack_hi2(x1, y1);
        g_Xl[(row0 + 8) * 512 + cp] = pack_lo2(x1, y1);
    }
}

// ============================ Launch ============================
extern "C" void kernel_launch(void* const* d_in, const int* in_sizes, int n_in,
                              void* d_out, int out_size)
{
    const float*        enc      = (const float*)d_in[0];
    const unsigned int* enc_mask = (const unsigned int*)d_in[1];
    const float*        dec      = (const float*)d_in[2];
    const float*        q_w      = (const float*)d_in[3];
    const float*        q_b      = (const float*)d_in[4];
    const float*        k_w      = (const float*)d_in[5];
    const float*        k_b      = (const float*)d_in[6];
    const float*        v_w      = (const float*)d_in[7];
    const float*        v_b      = (const float*)d_in[8];
    const float*        o_w      = (const float*)d_in[9];
    const float*        o_b      = (const float*)d_in[10];
    float*              out      = (float*)d_out;

    uint32_t *pdech, *pdecl, *pench, *pencl, *pwth, *pwtl;
    uint32_t *pQh, *pQl, *pKh, *pKl, *pVh, *pVl, *pXh, *pXl;
    cudaGetSymbolAddress((void**)&pdech, g_dech);
    cudaGetSymbolAddress((void**)&pdecl, g_decl);
    cudaGetSymbolAddress((void**)&pench, g_ench);
    cudaGetSymbolAddress((void**)&pencl, g_encl);
    cudaGetSymbolAddress((void**)&pwth,  g_wth);
    cudaGetSymbolAddress((void**)&pwtl,  g_wtl);
    cudaGetSymbolAddress((void**)&pQh,   g_Qh);
    cudaGetSymbolAddress((void**)&pQl,   g_Ql);
    cudaGetSymbolAddress((void**)&pKh,   g_Kh);
    cudaGetSymbolAddress((void**)&pKl,   g_Kl);
    cudaGetSymbolAddress((void**)&pVh,   g_Vh);
    cudaGetSymbolAddress((void**)&pVl,   g_Vl);
    cudaGetSymbolAddress((void**)&pXh,   g_Xh);
    cudaGetSymbolAddress((void**)&pXl,   g_Xl);

    const size_t WSZ = 1024 * 512;

    cudaFuncSetAttribute(hgemm, cudaFuncAttributeMaxDynamicSharedMemorySize, 81920);
    cudaFuncSetAttribute(attn_mma, cudaFuncAttributeMaxDynamicSharedMemorySize, ATTN_SMEM);

    // one-time converts
    conv_act<<<4096 * 512 / 256, 256>>>(dec, pdech, pdecl);
    conv_act<<<8192 * 512 / 256, 256>>>(enc, pench, pencl);
    conv_wt<<<dim3(32, 16), 256>>>(q_w, pwth + 0 * WSZ, pwtl + 0 * WSZ);
    conv_wt<<<dim3(32, 16), 256>>>(k_w, pwth + 1 * WSZ, pwtl + 1 * WSZ);
    conv_wt<<<dim3(32, 16), 256>>>(v_w, pwth + 2 * WSZ, pwtl + 2 * WSZ);
    conv_wt<<<dim3(32, 16), 256>>>(o_w, pwth + 3 * WSZ, pwtl + 3 * WSZ);

    // projections (packed outputs; CS folded into Q)
    hgemm<<<dim3(8, 32), 256, 81920>>>(pdech, pdecl, pwth + 0 * WSZ, pwtl + 0 * WSZ,
                                       q_b, nullptr, pQh, pQl, CS);
    hgemm<<<dim3(8, 64), 256, 81920>>>(pench, pencl, pwth + 1 * WSZ, pwtl + 1 * WSZ,
                                       k_b, nullptr, pKh, pKl, 1.0f);
    hgemm<<<dim3(8, 64), 256, 81920>>>(pench, pencl, pwth + 2 * WSZ, pwtl + 2 * WSZ,
                                       v_b, nullptr, pVh, pVl, 1.0f);

    // attention (reads packed Q/K/V globals, writes packed X globals)
    attn_mma<<<dim3(SDEC / 128, NH, BB), 256, ATTN_SMEM>>>(enc_mask);

    // output projection (fp32 out)
    hgemm<<<dim3(8, 32), 256, 81920>>>(pXh, pXl, pwth + 3 * WSZ, pwtl + 3 * WSZ,
                                       o_b, out, nullptr, nullptr, 1.0f);
}

// round 7
// speedup vs baseline: 2.4975x; 1.0378x over previous
#include <cuda_runtime.h>
#include <cuda_bf16.h>
#include <cstdint>

#define BB 4
#define SENC 2048
#define SDEC 1024
#define DIM 1024
#define NH 16
#define HD 64
#define CS (0.125f * 1.44269504088896f)   // 1/sqrt(64) * log2(e)

// ================= persistent packed-bf16 hi/lo scratch (uint32 = 2 bf16) ==
__device__ uint32_t g_dech[4096*512], g_decl[4096*512];
__device__ uint32_t g_ench[8192*512], g_encl[8192*512];
__device__ uint32_t g_wth[4][1024*512], g_wtl[4][1024*512];   // transposed [n][kpair]
__device__ uint32_t g_Qh[4096*512],  g_Ql[4096*512];          // CS pre-folded
__device__ uint32_t g_Kh[8192*512],  g_Kl[8192*512];
__device__ uint32_t g_Vh[8192*512],  g_Vl[8192*512];
__device__ uint32_t g_Xh[4096*512],  g_Xl[4096*512];

// ============================ helpers ============================
__device__ __forceinline__ uint32_t smem_u32(const void* p) {
    uint32_t a;
    asm("{ .reg .u64 t; cvta.to.shared.u64 t, %1; cvt.u32.u64 %0, t; }" : "=r"(a) : "l"(p));
    return a;
}
__device__ __forceinline__ uint32_t pack_hi2(float x, float y) {
    __nv_bfloat16 a = __float2bfloat16_rn(x), b = __float2bfloat16_rn(y);
    return (uint32_t)__bfloat16_as_ushort(a) | ((uint32_t)__bfloat16_as_ushort(b) << 16);
}
__device__ __forceinline__ uint32_t pack_lo2(float x, float y) {
    __nv_bfloat16 a = __float2bfloat16_rn(x), b = __float2bfloat16_rn(y);
    __nv_bfloat16 la = __float2bfloat16_rn(x - __bfloat162float(a));
    __nv_bfloat16 lb = __float2bfloat16_rn(y - __bfloat162float(b));
    return (uint32_t)__bfloat16_as_ushort(la) | ((uint32_t)__bfloat16_as_ushort(lb) << 16);
}
__device__ __forceinline__ void mma_bf16(float* d, const uint32_t* a, const uint32_t* b) {
    asm volatile("mma.sync.aligned.m16n8k16.row.col.f32.bf16.bf16.f32 "
        "{%0,%1,%2,%3}, {%4,%5,%6,%7}, {%8,%9}, {%0,%1,%2,%3};"
        : "+f"(d[0]), "+f"(d[1]), "+f"(d[2]), "+f"(d[3])
        : "r"(a[0]), "r"(a[1]), "r"(a[2]), "r"(a[3]), "r"(b[0]), "r"(b[1]));
}
__device__ __forceinline__ void ldmx4(uint32_t* r, uint32_t addr) {
    asm volatile("ldmatrix.sync.aligned.m8n8.x4.shared.b16 {%0,%1,%2,%3}, [%4];"
        : "=r"(r[0]), "=r"(r[1]), "=r"(r[2]), "=r"(r[3]) : "r"(addr));
}
__device__ __forceinline__ void ldmx4_trans(uint32_t* r, uint32_t addr) {
    asm volatile("ldmatrix.sync.aligned.m8n8.x4.trans.shared.b16 {%0,%1,%2,%3}, [%4];"
        : "=r"(r[0]), "=r"(r[1]), "=r"(r[2]), "=r"(r[3]) : "r"(addr));
}
// exp2 on FMA/ALU pipes. u <= 0.
__device__ __forceinline__ float exp2p(float u) {
    u = fmaxf(u, -60.0f);
    float n = rintf(u);
    float f = u - n;
    float p = 0.0013333558f;
    p = fmaf(p, f, 0.0096181291f);
    p = fmaf(p, f, 0.0555041087f);
    p = fmaf(p, f, 0.2402265070f);
    p = fmaf(p, f, 0.6931471806f);
    p = fmaf(p, f, 1.0f);
    int sb = (__float2int_rn(n) + 127) << 23;
    return p * __int_as_float(sb);
}
#define CP16(dst, src) \
    asm volatile("cp.async.cg.shared.global [%0], [%1], 16;" :: "r"(dst), "l"(src) : "memory")
#define CP_COMMIT() asm volatile("cp.async.commit_group;" ::: "memory")
#define CP_WAIT1()  asm volatile("cp.async.wait_group 1;" ::: "memory")

// ============================ convert kernels ============================
__global__ __launch_bounds__(256) void conv_act(
    const float* __restrict__ A, uint32_t* __restrict__ H, uint32_t* __restrict__ L)
{
    int i = blockIdx.x * 256 + threadIdx.x;
    float2 v = ((const float2*)A)[i];
    H[i] = pack_hi2(v.x, v.y);
    L[i] = pack_lo2(v.x, v.y);
}

__global__ __launch_bounds__(256) void conv_wt(
    const float* __restrict__ W, uint32_t* __restrict__ Th, uint32_t* __restrict__ Tl)
{
    __shared__ float tile[64][33];
    int k0 = blockIdx.y * 64, n0 = blockIdx.x * 32;
    int tx = threadIdx.x & 31, ty = threadIdx.x >> 5;
    for (int r = ty; r < 64; r += 8)
        tile[r][tx] = W[(size_t)(k0 + r) * 1024 + n0 + tx];
    __syncthreads();
    for (int nn = ty; nn < 32; nn += 8) {
        float a = tile[2 * tx][nn], b = tile[2 * tx + 1][nn];
        Th[(size_t)(n0 + nn) * 512 + (k0 >> 1) + tx] = pack_hi2(a, b);
        Tl[(size_t)(n0 + nn) * 512 + (k0 >> 1) + tx] = pack_lo2(a, b);
    }
}

// ============================ HMMA GEMM (pre-packed, ldmatrix) ============
#define AST 20   // smem row stride in uint32

__global__ __launch_bounds__(256) void hgemm(
    const uint32_t* __restrict__ Ah, const uint32_t* __restrict__ Al,
    const uint32_t* __restrict__ Bth, const uint32_t* __restrict__ Btl,
    const float* __restrict__ bias,
    float* __restrict__ Cf, uint32_t* __restrict__ Ch, uint32_t* __restrict__ Cl,
    float scale)
{
    extern __shared__ uint32_t smu[];
    const uint32_t sb = smem_u32(smu);
    const int t = threadIdx.x, lane = t & 31, wid = t >> 5;
    const int g = lane >> 2, tq = lane & 3;
    const int wm = wid & 1, wn = wid >> 1;
    const int bm = blockIdx.y * 128, bn = blockIdx.x * 128;

    float acc[4][4][4];
#pragma unroll
    for (int i = 0; i < 4; i++)
#pragma unroll
        for (int j = 0; j < 4; j++)
#pragma unroll
            for (int k = 0; k < 4; k++) acc[i][j][k] = 0.f;

    auto issue = [&](int kb, int st) {
        const uint32_t base = sb + st * 40960;
        const int row = t >> 2, ch = t & 3;
#pragma unroll
        for (int c = 0; c < 8; c++) {
            int tile = c >> 1;
            int r = (c & 1) * 64 + row;
            const uint32_t* src = (tile == 0) ? Ah : (tile == 1) ? Al
                                : (tile == 2) ? Bth : Btl;
            int grow = ((tile < 2) ? bm : bn) + r;
            CP16(base + (uint32_t)(tile * 2560 + r * AST + ch * 4) * 4,
                 src + (size_t)grow * 512 + (kb >> 1) + ch * 4);
        }
    };

    issue(0, 0);
    CP_COMMIT();

    // ldmatrix per-lane address components
    const uint32_t a_row = (uint32_t)(wm * 64 + (lane & 15));    // + mi*16
    const uint32_t a_k8  = (uint32_t)((lane >> 4) * 16);         // byte offset of k8-half
    const uint32_t bsel  = (uint32_t)(lane >> 3);                // 0..3
    const uint32_t b_row = (uint32_t)(wn * 32 + (bsel >> 1) * 8 + (lane & 7));  // + p*16
    const uint32_t b_k8  = (uint32_t)((bsel & 1) * 16);

    for (int i = 0; i < 32; i++) {
        int kb = i * 32;
        if (i + 1 < 32) issue(kb + 32, (i + 1) & 1);
        CP_COMMIT();
        CP_WAIT1();
        __syncthreads();

        const uint32_t stb = sb + (i & 1) * 40960;   // Ah@0 Al@10240 Bh@20480 Bl@30720 bytes

#pragma unroll
        for (int ks = 0; ks < 2; ks++) {
            uint32_t ah[4][4], al[4][4], bh[4][2], bl[4][2];
#pragma unroll
            for (int mi = 0; mi < 4; mi++) {
                uint32_t aa = stb + (a_row + mi * 16) * (AST * 4) + ks * 32 + a_k8;
                ldmx4(ah[mi], aa);
                ldmx4(al[mi], aa + 10240);
            }
#pragma unroll
            for (int p = 0; p < 2; p++) {
                uint32_t ba = stb + 20480 + (b_row + p * 16) * (AST * 4) + ks * 32 + b_k8;
                uint32_t rh[4], rl[4];
                ldmx4(rh, ba);
                ldmx4(rl, ba + 10240);
                bh[2 * p][0] = rh[0]; bh[2 * p][1] = rh[1];
                bh[2 * p + 1][0] = rh[2]; bh[2 * p + 1][1] = rh[3];
                bl[2 * p][0] = rl[0]; bl[2 * p][1] = rl[1];
                bl[2 * p + 1][0] = rl[2]; bl[2 * p + 1][1] = rl[3];
            }
#pragma unroll
            for (int mi = 0; mi < 4; mi++)
#pragma unroll
                for (int ni = 0; ni < 4; ni++) {
                    mma_bf16(acc[mi][ni], ah[mi], bh[ni]);
                    mma_bf16(acc[mi][ni], ah[mi], bl[ni]);
                    mma_bf16(acc[mi][ni], al[mi], bh[ni]);
                }
        }
        __syncthreads();
    }

#pragma unroll
    for (int mi = 0; mi < 4; mi++) {
        int r0 = bm + wm * 64 + mi * 16 + g;
#pragma unroll
        for (int ni = 0; ni < 4; ni++) {
            int c = bn + wn * 32 + ni * 8 + 2 * tq;
            float2 bb = *(const float2*)(bias + c);
            float* d = acc[mi][ni];
            if (Cf) {
                *(float2*)(Cf + (size_t)r0 * 1024 + c) =
                    make_float2(d[0] + bb.x, d[1] + bb.y);
                *(float2*)(Cf + (size_t)(r0 + 8) * 1024 + c) =
                    make_float2(d[2] + bb.x, d[3] + bb.y);
            } else {
                float x0 = (d[0] + bb.x) * scale, y0 = (d[1] + bb.y) * scale;
                float x1 = (d[2] + bb.x) * scale, y1 = (d[3] + bb.y) * scale;
                size_t cp = (size_t)(c >> 1);
                Ch[(size_t)r0 * 512 + cp]       = pack_hi2(x0, y0);
                Cl[(size_t)r0 * 512 + cp]       = pack_lo2(x0, y0);
                Ch[(size_t)(r0 + 8) * 512 + cp] = pack_hi2(x1, y1);
                Cl[(size_t)(r0 + 8) * 512 + cp] = pack_lo2(x1, y1);
            }
        }
    }
}

// ============================ FA2 attention (ldmatrix K + V) =============
#define ATTN_SMEM (2 * 36864)

__global__ __launch_bounds__(256, 1) void attn_mma(const unsigned int* __restrict__ mask)
{
    extern __shared__ uint32_t smu[];
    const uint32_t sb = smem_u32(smu);
    const int t = threadIdx.x, w = t >> 5, lane = t & 31;
    const int g = lane >> 2, tq = lane & 3;
    const int qt = blockIdx.x, h = blockIdx.y, b = blockIdx.z;
    const int q0 = qt * 128;
    const unsigned int* mk = mask + (size_t)b * SENC;

    const size_t qrow = (size_t)(b * SDEC + q0 + 16 * w);
    uint32_t qh[4][4], ql[4][4];
#pragma unroll
    for (int ks = 0; ks < 4; ks++) {
        size_t p0 = (qrow + g) * 512 + h * 32 + ks * 8 + tq;
        size_t p1 = (qrow + g + 8) * 512 + h * 32 + ks * 8 + tq;
        qh[ks][0] = g_Qh[p0]; qh[ks][1] = g_Qh[p1];
        qh[ks][2] = g_Qh[p0 + 4]; qh[ks][3] = g_Qh[p1 + 4];
        ql[ks][0] = g_Ql[p0]; ql[ks][1] = g_Ql[p1];
        ql[ks][2] = g_Ql[p0 + 4]; ql[ks][3] = g_Ql[p1 + 4];
    }

    float m0 = -1e30f, m1 = -1e30f, l0 = 0.f, l1 = 0.f;
    float oacc[8][4];
#pragma unroll
    for (int ni = 0; ni < 8; ni++)
#pragma unroll
        for (int k = 0; k < 4; k++) oacc[ni][k] = 0.f;

    auto issue = [&](int kb, int st) {
        const uint32_t base = sb + st * 36864;
        const uint32_t* srcs[4] = {g_Kh, g_Kl, g_Vh, g_Vl};
        const int keyl = t >> 3, ch = t & 7;
#pragma unroll
        for (int c = 0; c < 8; c++) {
            int tile = c >> 1;
            int key = (c & 1) * 32 + keyl;
            CP16(base + (uint32_t)(tile * 9216 + key * 144 + ch * 16),
                 srcs[tile] + (size_t)(b * SENC + kb + key) * 512 + h * 32 + ch * 4);
        }
    };

    issue(0, 0);
    CP_COMMIT();

    // K ldmatrix lane addressing: pair p covers n-groups 2p, 2p+1
    const uint32_t ksel  = (uint32_t)(lane >> 3);
    const uint32_t k_row = (uint32_t)((ksel >> 1) * 8 + (lane & 7));   // + p*16
    const uint32_t k_k8  = (uint32_t)((ksel & 1) * 16);

    for (int i = 0; i < SENC / 64; i++) {
        const int k0 = i * 64, st = i & 1;
        if (i + 1 < SENC / 64) issue((i + 1) * 64, (i + 1) & 1);
        CP_COMMIT();
        CP_WAIT1();
        __syncthreads();

        const uint32_t kbase = sb + st * 36864;          // Kh; Kl at +9216
        const uint32_t vbase = kbase + 18432;            // Vh; Vl at +9216

        // ---- S = Q K^T (3-pass) ----
        float sacc[8][4];
#pragma unroll
        for (int ni = 0; ni < 8; ni++)
#pragma unroll
            for (int k = 0; k < 4; k++) sacc[ni][k] = 0.f;
#pragma unroll
        for (int ks = 0; ks < 4; ks++) {
#pragma unroll
            for (int p = 0; p < 4; p++) {
                uint32_t ka = kbase + (k_row + p * 16) * 144 + ks * 32 + k_k8;
                uint32_t rh[4], rl[4];
                ldmx4(rh, ka);
                ldmx4(rl, ka + 9216);
                mma_bf16(sacc[2 * p],     qh[ks], &rh[0]);
                mma_bf16(sacc[2 * p],     ql[ks], &rh[0]);
                mma_bf16(sacc[2 * p],     qh[ks], &rl[0]);
                mma_bf16(sacc[2 * p + 1], qh[ks], &rh[2]);
                mma_bf16(sacc[2 * p + 1], ql[ks], &rh[2]);
                mma_bf16(sacc[2 * p + 1], qh[ks], &rl[2]);
            }
        }

        // ---- mask ----
#pragma unroll
        for (int ni = 0; ni < 8; ni++) {
            uint2 mw = *(const uint2*)(mk + k0 + 8 * ni + 2 * tq);
            if (mw.x) { sacc[ni][0] = -1e30f; sacc[ni][2] = -1e30f; }
            if (mw.y) { sacc[ni][1] = -1e30f; sacc[ni][3] = -1e30f; }
        }

        // ---- online softmax (base-2) ----
        float v0 = -1e30f, v1 = -1e30f;
#pragma unroll
        for (int ni = 0; ni < 8; ni++) {
            v0 = fmaxf(v0, fmaxf(sacc[ni][0], sacc[ni][1]));
            v1 = fmaxf(v1, fmaxf(sacc[ni][2], sacc[ni][3]));
        }
        v0 = fmaxf(v0, __shfl_xor_sync(0xffffffffu, v0, 1));
        v0 = fmaxf(v0, __shfl_xor_sync(0xffffffffu, v0, 2));
        v1 = fmaxf(v1, __shfl_xor_sync(0xffffffffu, v1, 1));
        v1 = fmaxf(v1, __shfl_xor_sync(0xffffffffu, v1, 2));
        float mn0 = fmaxf(m0, v0), mn1 = fmaxf(m1, v1);
        float al0 = exp2p(m0 - mn0), al1 = exp2p(m1 - mn1);
        m0 = mn0; m1 = mn1;

        float rs0 = 0.f, rs1 = 0.f;
#pragma unroll
        for (int ni = 0; ni < 8; ni++) {
            sacc[ni][0] = exp2p(sacc[ni][0] - mn0); rs0 += sacc[ni][0];
            sacc[ni][1] = exp2p(sacc[ni][1] - mn0); rs0 += sacc[ni][1];
            sacc[ni][2] = exp2p(sacc[ni][2] - mn1); rs1 += sacc[ni][2];
            sacc[ni][3] = exp2p(sacc[ni][3] - mn1); rs1 += sacc[ni][3];
        }
        rs0 += __shfl_xor_sync(0xffffffffu, rs0, 1);
        rs0 += __shfl_xor_sync(0xffffffffu, rs0, 2);
        rs1 += __shfl_xor_sync(0xffffffffu, rs1, 1);
        rs1 += __shfl_xor_sync(0xffffffffu, rs1, 2);
        l0 = l0 * al0 + rs0;
        l1 = l1 * al1 + rs1;
#pragma unroll
        for (int ni = 0; ni < 8; ni++) {
            oacc[ni][0] *= al0; oacc[ni][1] *= al0;
            oacc[ni][2] *= al1; oacc[ni][3] *= al1;
        }

        // ---- P fragments ----
        uint32_t pah[4][4], pal[4][4];
#pragma unroll
        for (int j = 0; j < 4; j++) {
            pah[j][0] = pack_hi2(sacc[2 * j][0], sacc[2 * j][1]);
            pal[j][0] = pack_lo2(sacc[2 * j][0], sacc[2 * j][1]);
            pah[j][1] = pack_hi2(sacc[2 * j][2], sacc[2 * j][3]);
            pal[j][1] = pack_lo2(sacc[2 * j][2], sacc[2 * j][3]);
            pah[j][2] = pack_hi2(sacc[2 * j + 1][0], sacc[2 * j + 1][1]);
            pal[j][2] = pack_lo2(sacc[2 * j + 1][0], sacc[2 * j + 1][1]);
            pah[j][3] = pack_hi2(sacc[2 * j + 1][2], sacc[2 * j + 1][3]);
            pal[j][3] = pack_lo2(sacc[2 * j + 1][2], sacc[2 * j + 1][3]);
        }

        // ---- O += P V (3-pass), V via ldmatrix.trans ----
#pragma unroll
        for (int j = 0; j < 4; j++) {
            uint32_t rowoff = (uint32_t)((16 * j + (lane & 15)) * 144);
#pragma unroll
            for (int n2 = 0; n2 < 8; n2 += 2) {
                uint32_t va = vbase + rowoff + n2 * 16 + ((lane >> 4) & 1) * 16;
                uint32_t vrh[4], vrl[4];
                ldmx4_trans(vrh, va);
                ldmx4_trans(vrl, va + 9216);
                mma_bf16(oacc[n2],     pah[j], &vrh[0]);
                mma_bf16(oacc[n2],     pal[j], &vrh[0]);
                mma_bf16(oacc[n2],     pah[j], &vrl[0]);
                mma_bf16(oacc[n2 + 1], pah[j], &vrh[2]);
                mma_bf16(oacc[n2 + 1], pal[j], &vrh[2]);
                mma_bf16(oacc[n2 + 1], pah[j], &vrl[2]);
            }
        }
        __syncthreads();
    }

    // ---- normalize + write packed X ----
    float inv0 = 1.0f / l0, inv1 = 1.0f / l1;
    const size_t row0 = qrow + g;
#pragma unroll
    for (int ni = 0; ni < 8; ni++) {
        size_t cp = (size_t)(h * 32 + ni * 4 + tq);
        float x0 = oacc[ni][0] * inv0, y0 = oacc[ni][1] * inv0;
        float x1 = oacc[ni][2] * inv1, y1 = oacc[ni][3] * inv1;
        g_Xh[row0 * 512 + cp]       = pack_hi2(x0, y0);
        g_Xl[row0 * 512 + cp]       = pack_lo2(x0, y0);
        g_Xh[(row0 + 8) * 512 + cp] = pack_hi2(x1, y1);
        g_Xl[(row0 + 8) * 512 + cp] = pack_lo2(x1, y1);
    }
}

// ============================ Launch ============================
extern "C" void kernel_launch(void* const* d_in, const int* in_sizes, int n_in,
                              void* d_out, int out_size)
{
    const float*        enc      = (const float*)d_in[0];
    const unsigned int* enc_mask = (const unsigned int*)d_in[1];
    const float*        dec      = (const float*)d_in[2];
    const float*        q_w      = (const float*)d_in[3];
    const float*        q_b      = (const float*)d_in[4];
    const float*        k_w      = (const float*)d_in[5];
    const float*        k_b      = (const float*)d_in[6];
    const float*        v_w      = (const float*)d_in[7];
    const float*        v_b      = (const float*)d_in[8];
    const float*        o_w      = (const float*)d_in[9];
    const float*        o_b      = (const float*)d_in[10];
    float*              out      = (float*)d_out;

    uint32_t *pdech, *pdecl, *pench, *pencl, *pwth, *pwtl;
    uint32_t *pQh, *pQl, *pKh, *pKl, *pVh, *pVl, *pXh, *pXl;
    cudaGetSymbolAddress((void**)&pdech, g_dech);
    cudaGetSymbolAddress((void**)&pdecl, g_decl);
    cudaGetSymbolAddress((void**)&pench, g_ench);
    cudaGetSymbolAddress((void**)&pencl, g_encl);
    cudaGetSymbolAddress((void**)&pwth,  g_wth);
    cudaGetSymbolAddress((void**)&pwtl,  g_wtl);
    cudaGetSymbolAddress((void**)&pQh,   g_Qh);
    cudaGetSymbolAddress((void**)&pQl,   g_Ql);
    cudaGetSymbolAddress((void**)&pKh,   g_Kh);
    cudaGetSymbolAddress((void**)&pKl,   g_Kl);
    cudaGetSymbolAddress((void**)&pVh,   g_Vh);
    cudaGetSymbolAddress((void**)&pVl,   g_Vl);
    cudaGetSymbolAddress((void**)&pXh,   g_Xh);
    cudaGetSymbolAddress((void**)&pXl,   g_Xl);

    const size_t WSZ = 1024 * 512;

    cudaFuncSetAttribute(hgemm, cudaFuncAttributeMaxDynamicSharedMemorySize, 81920);
    cudaFuncSetAttribute(attn_mma, cudaFuncAttributeMaxDynamicSharedMemorySize, ATTN_SMEM);

    conv_act<<<4096 * 512 / 256, 256>>>(dec, pdech, pdecl);
    conv_act<<<8192 * 512 / 256, 256>>>(enc, pench, pencl);
    conv_wt<<<dim3(32, 16), 256>>>(q_w, pwth + 0 * WSZ, pwtl + 0 * WSZ);
    conv_wt<<<dim3(32, 16), 256>>>(k_w, pwth + 1 * WSZ, pwtl + 1 * WSZ);
    conv_wt<<<dim3(32, 16), 256>>>(v_w, pwth + 2 * WSZ, pwtl + 2 * WSZ);
    conv_wt<<<dim3(32, 16), 256>>>(o_w, pwth + 3 * WSZ, pwtl + 3 * WSZ);

    hgemm<<<dim3(8, 32), 256, 81920>>>(pdech, pdecl, pwth + 0 * WSZ, pwtl + 0 * WSZ,
                                       q_b, nullptr, pQh, pQl, CS);
    hgemm<<<dim3(8, 64), 256, 81920>>>(pench, pencl, pwth + 1 * WSZ, pwtl + 1 * WSZ,
                                       k_b, nullptr, pKh, pKl, 1.0f);
    hgemm<<<dim3(8, 64), 256, 81920>>>(pench, pencl, pwth + 2 * WSZ, pwtl + 2 * WSZ,
                                       v_b, nullptr, pVh, pVl, 1.0f);

    attn_mma<<<dim3(SDEC / 128, NH, BB), 256, ATTN_SMEM>>>(enc_mask);

    hgemm<<<dim3(8, 32), 256, 81920>>>(pXh, pXl, pwth + 3 * WSZ, pwtl + 3 * WSZ,
                                       o_b, out, nullptr, nullptr, 1.0f);
}

// round 8
// speedup vs baseline: 2.6884x; 1.0764x over previous
#include <cuda_runtime.h>
#include <cuda_bf16.h>
#include <cstdint>

#define BB 4
#define SENC 2048
#define SDEC 1024
#define DIM 1024
#define NH 16
#define HD 64
#define CS (0.125f * 1.44269504088896f)   // 1/sqrt(64) * log2(e)

// ================= persistent packed-bf16 hi/lo scratch (uint32 = 2 bf16) ==
__device__ uint32_t g_dech[4096*512], g_decl[4096*512];
__device__ uint32_t g_ench[8192*512], g_encl[8192*512];
__device__ uint32_t g_wth[4][1024*512], g_wtl[4][1024*512];   // transposed [n][kpair]
__device__ uint32_t g_Qh[4096*512],  g_Ql[4096*512];          // CS pre-folded
__device__ uint32_t g_Kh[8192*512],  g_Kl[8192*512];
__device__ uint32_t g_Vh[8192*512],  g_Vl[8192*512];
__device__ uint32_t g_Xh[4096*512],  g_Xl[4096*512];

// ============================ helpers ============================
__device__ __forceinline__ uint32_t smem_u32(const void* p) {
    uint32_t a;
    asm("{ .reg .u64 t; cvta.to.shared.u64 t, %1; cvt.u32.u64 %0, t; }" : "=r"(a) : "l"(p));
    return a;
}
__device__ __forceinline__ uint32_t pack_hi2(float x, float y) {
    __nv_bfloat16 a = __float2bfloat16_rn(x), b = __float2bfloat16_rn(y);
    return (uint32_t)__bfloat16_as_ushort(a) | ((uint32_t)__bfloat16_as_ushort(b) << 16);
}
__device__ __forceinline__ uint32_t pack_lo2(float x, float y) {
    __nv_bfloat16 a = __float2bfloat16_rn(x), b = __float2bfloat16_rn(y);
    __nv_bfloat16 la = __float2bfloat16_rn(x - __bfloat162float(a));
    __nv_bfloat16 lb = __float2bfloat16_rn(y - __bfloat162float(b));
    return (uint32_t)__bfloat16_as_ushort(la) | ((uint32_t)__bfloat16_as_ushort(lb) << 16);
}
__device__ __forceinline__ void mma_bf16(float* d, const uint32_t* a, const uint32_t* b) {
    asm volatile("mma.sync.aligned.m16n8k16.row.col.f32.bf16.bf16.f32 "
        "{%0,%1,%2,%3}, {%4,%5,%6,%7}, {%8,%9}, {%0,%1,%2,%3};"
        : "+f"(d[0]), "+f"(d[1]), "+f"(d[2]), "+f"(d[3])
        : "r"(a[0]), "r"(a[1]), "r"(a[2]), "r"(a[3]), "r"(b[0]), "r"(b[1]));
}
__device__ __forceinline__ void ldmx4(uint32_t* r, uint32_t addr) {
    asm volatile("ldmatrix.sync.aligned.m8n8.x4.shared.b16 {%0,%1,%2,%3}, [%4];"
        : "=r"(r[0]), "=r"(r[1]), "=r"(r[2]), "=r"(r[3]) : "r"(addr));
}
__device__ __forceinline__ void ldmx4_trans(uint32_t* r, uint32_t addr) {
    asm volatile("ldmatrix.sync.aligned.m8n8.x4.trans.shared.b16 {%0,%1,%2,%3}, [%4];"
        : "=r"(r[0]), "=r"(r[1]), "=r"(r[2]), "=r"(r[3]) : "r"(addr));
}
// exp2 on FMA/ALU pipes. u <= 0.
__device__ __forceinline__ float exp2p(float u) {
    u = fmaxf(u, -60.0f);
    float n = rintf(u);
    float f = u - n;
    float p = 0.0013333558f;
    p = fmaf(p, f, 0.0096181291f);
    p = fmaf(p, f, 0.0555041087f);
    p = fmaf(p, f, 0.2402265070f);
    p = fmaf(p, f, 0.6931471806f);
    p = fmaf(p, f, 1.0f);
    int sb = (__float2int_rn(n) + 127) << 23;
    return p * __int_as_float(sb);
}
#define CP16(dst, src) \
    asm volatile("cp.async.cg.shared.global [%0], [%1], 16;" :: "r"(dst), "l"(src) : "memory")
#define CP_COMMIT() asm volatile("cp.async.commit_group;" ::: "memory")
#define CP_WAIT1()  asm volatile("cp.async.wait_group 1;" ::: "memory")

// ============================ convert kernels (fused) ====================
// dec (4096 rows) + enc (8192 rows) in one launch
__global__ __launch_bounds__(256) void conv_act_all(
    const float* __restrict__ dec, const float* __restrict__ enc,
    uint32_t* __restrict__ DH, uint32_t* __restrict__ DL,
    uint32_t* __restrict__ EH, uint32_t* __restrict__ EL)
{
    int i = blockIdx.x * 256 + threadIdx.x;
    const int NDEC = 4096 * 512;
    if (i < NDEC) {
        float2 v = ((const float2*)dec)[i];
        DH[i] = pack_hi2(v.x, v.y);
        DL[i] = pack_lo2(v.x, v.y);
    } else {
        int j = i - NDEC;
        float2 v = ((const float2*)enc)[j];
        EH[j] = pack_hi2(v.x, v.y);
        EL[j] = pack_lo2(v.x, v.y);
    }
}

// all 4 weights, blockIdx.z selects which
__global__ __launch_bounds__(256) void conv_wt_all(
    const float* __restrict__ W0, const float* __restrict__ W1,
    const float* __restrict__ W2, const float* __restrict__ W3,
    uint32_t* __restrict__ Th, uint32_t* __restrict__ Tl)
{
    __shared__ float tile[64][33];
    const float* W = (blockIdx.z == 0) ? W0 : (blockIdx.z == 1) ? W1
                   : (blockIdx.z == 2) ? W2 : W3;
    uint32_t* Thz = Th + (size_t)blockIdx.z * (1024 * 512);
    uint32_t* Tlz = Tl + (size_t)blockIdx.z * (1024 * 512);
    int k0 = blockIdx.y * 64, n0 = blockIdx.x * 32;
    int tx = threadIdx.x & 31, ty = threadIdx.x >> 5;
    for (int r = ty; r < 64; r += 8)
        tile[r][tx] = W[(size_t)(k0 + r) * 1024 + n0 + tx];
    __syncthreads();
    for (int nn = ty; nn < 32; nn += 8) {
        float a = tile[2 * tx][nn], b = tile[2 * tx + 1][nn];
        Thz[(size_t)(n0 + nn) * 512 + (k0 >> 1) + tx] = pack_hi2(a, b);
        Tlz[(size_t)(n0 + nn) * 512 + (k0 >> 1) + tx] = pack_lo2(a, b);
    }
}

// ============================ HMMA GEMM (pre-packed, ldmatrix) ============
#define AST 20   // smem row stride in uint32

__global__ __launch_bounds__(256) void hgemm(
    const uint32_t* __restrict__ Ah, const uint32_t* __restrict__ Al,
    const uint32_t* __restrict__ Bth, const uint32_t* __restrict__ Btl,
    const float* __restrict__ bias,
    float* __restrict__ Cf, uint32_t* __restrict__ Ch, uint32_t* __restrict__ Cl,
    float scale)
{
    extern __shared__ uint32_t smu[];
    const uint32_t sb = smem_u32(smu);
    const int t = threadIdx.x, lane = t & 31, wid = t >> 5;
    const int g = lane >> 2, tq = lane & 3;
    const int wm = wid & 1, wn = wid >> 1;
    const int bm = blockIdx.y * 128, bn = blockIdx.x * 128;

    float acc[4][4][4];
#pragma unroll
    for (int i = 0; i < 4; i++)
#pragma unroll
        for (int j = 0; j < 4; j++)
#pragma unroll
            for (int k = 0; k < 4; k++) acc[i][j][k] = 0.f;

    auto issue = [&](int kb, int st) {
        const uint32_t base = sb + st * 40960;
        const int row = t >> 2, ch = t & 3;
#pragma unroll
        for (int c = 0; c < 8; c++) {
            int tile = c >> 1;
            int r = (c & 1) * 64 + row;
            const uint32_t* src = (tile == 0) ? Ah : (tile == 1) ? Al
                                : (tile == 2) ? Bth : Btl;
            int grow = ((tile < 2) ? bm : bn) + r;
            CP16(base + (uint32_t)(tile * 2560 + r * AST + ch * 4) * 4,
                 src + (size_t)grow * 512 + (kb >> 1) + ch * 4);
        }
    };

    issue(0, 0);
    CP_COMMIT();

    const uint32_t a_row = (uint32_t)(wm * 64 + (lane & 15));
    const uint32_t a_k8  = (uint32_t)((lane >> 4) * 16);
    const uint32_t bsel  = (uint32_t)(lane >> 3);
    const uint32_t b_row = (uint32_t)(wn * 32 + (bsel >> 1) * 8 + (lane & 7));
    const uint32_t b_k8  = (uint32_t)((bsel & 1) * 16);

    for (int i = 0; i < 32; i++) {
        int kb = i * 32;
        if (i + 1 < 32) issue(kb + 32, (i + 1) & 1);
        CP_COMMIT();
        CP_WAIT1();
        __syncthreads();

        const uint32_t stb = sb + (i & 1) * 40960;

#pragma unroll
        for (int ks = 0; ks < 2; ks++) {
            uint32_t ah[4][4], al[4][4], bh[4][2], bl[4][2];
#pragma unroll
            for (int mi = 0; mi < 4; mi++) {
                uint32_t aa = stb + (a_row + mi * 16) * (AST * 4) + ks * 32 + a_k8;
                ldmx4(ah[mi], aa);
                ldmx4(al[mi], aa + 10240);
            }
#pragma unroll
            for (int p = 0; p < 2; p++) {
                uint32_t ba = stb + 20480 + (b_row + p * 16) * (AST * 4) + ks * 32 + b_k8;
                uint32_t rh[4], rl[4];
                ldmx4(rh, ba);
                ldmx4(rl, ba + 10240);
                bh[2 * p][0] = rh[0]; bh[2 * p][1] = rh[1];
                bh[2 * p + 1][0] = rh[2]; bh[2 * p + 1][1] = rh[3];
                bl[2 * p][0] = rl[0]; bl[2 * p][1] = rl[1];
                bl[2 * p + 1][0] = rl[2]; bl[2 * p + 1][1] = rl[3];
            }
#pragma unroll
            for (int mi = 0; mi < 4; mi++)
#pragma unroll
                for (int ni = 0; ni < 4; ni++) {
                    mma_bf16(acc[mi][ni], ah[mi], bh[ni]);
                    mma_bf16(acc[mi][ni], ah[mi], bl[ni]);
                    mma_bf16(acc[mi][ni], al[mi], bh[ni]);
                }
        }
        __syncthreads();
    }

#pragma unroll
    for (int mi = 0; mi < 4; mi++) {
        int r0 = bm + wm * 64 + mi * 16 + g;
#pragma unroll
        for (int ni = 0; ni < 4; ni++) {
            int c = bn + wn * 32 + ni * 8 + 2 * tq;
            float2 bb = *(const float2*)(bias + c);
            float* d = acc[mi][ni];
            if (Cf) {
                *(float2*)(Cf + (size_t)r0 * 1024 + c) =
                    make_float2(d[0] + bb.x, d[1] + bb.y);
                *(float2*)(Cf + (size_t)(r0 + 8) * 1024 + c) =
                    make_float2(d[2] + bb.x, d[3] + bb.y);
            } else {
                float x0 = (d[0] + bb.x) * scale, y0 = (d[1] + bb.y) * scale;
                float x1 = (d[2] + bb.x) * scale, y1 = (d[3] + bb.y) * scale;
                size_t cp = (size_t)(c >> 1);
                Ch[(size_t)r0 * 512 + cp]       = pack_hi2(x0, y0);
                Cl[(size_t)r0 * 512 + cp]       = pack_lo2(x0, y0);
                Ch[(size_t)(r0 + 8) * 512 + cp] = pack_hi2(x1, y1);
                Cl[(size_t)(r0 + 8) * 512 + cp] = pack_lo2(x1, y1);
            }
        }
    }
}

// ============================ FA2 attention: 4 warps, 64 q rows ==========
// 2 blocks/SM (regs ~184 x 128 thr x 2 = 47K; smem 73728 x 2 = 147K).
#define ATTN_SMEM (2 * 36864)

__global__ __launch_bounds__(128, 2) void attn_mma(const unsigned int* __restrict__ mask)
{
    extern __shared__ uint32_t smu[];
    const uint32_t sb = smem_u32(smu);
    const int t = threadIdx.x, w = t >> 5, lane = t & 31;
    const int g = lane >> 2, tq = lane & 3;
    const int qt = blockIdx.x, h = blockIdx.y, b = blockIdx.z;
    const int q0 = qt * 64;
    const unsigned int* mk = mask + (size_t)b * SENC;

    const size_t qrow = (size_t)(b * SDEC + q0 + 16 * w);
    uint32_t qh[4][4], ql[4][4];
#pragma unroll
    for (int ks = 0; ks < 4; ks++) {
        size_t p0 = (qrow + g) * 512 + h * 32 + ks * 8 + tq;
        size_t p1 = (qrow + g + 8) * 512 + h * 32 + ks * 8 + tq;
        qh[ks][0] = g_Qh[p0]; qh[ks][1] = g_Qh[p1];
        qh[ks][2] = g_Qh[p0 + 4]; qh[ks][3] = g_Qh[p1 + 4];
        ql[ks][0] = g_Ql[p0]; ql[ks][1] = g_Ql[p1];
        ql[ks][2] = g_Ql[p0 + 4]; ql[ks][3] = g_Ql[p1 + 4];
    }

    float m0 = -1e30f, m1 = -1e30f, l0 = 0.f, l1 = 0.f;
    float oacc[8][4];
#pragma unroll
    for (int ni = 0; ni < 8; ni++)
#pragma unroll
        for (int k = 0; k < 4; k++) oacc[ni][k] = 0.f;

    // 128 threads fill 4 tiles x 64 keys x 128B (stride 144B)
    auto issue = [&](int kb, int st) {
        const uint32_t base = sb + st * 36864;
        const uint32_t* srcs[4] = {g_Kh, g_Kl, g_Vh, g_Vl};
        const int keyl = t >> 3, ch = t & 7;
#pragma unroll
        for (int c = 0; c < 16; c++) {
            int tile = c >> 2;
            int key = (c & 3) * 16 + keyl;
            CP16(base + (uint32_t)(tile * 9216 + key * 144 + ch * 16),
                 srcs[tile] + (size_t)(b * SENC + kb + key) * 512 + h * 32 + ch * 4);
        }
    };

    issue(0, 0);
    CP_COMMIT();

    const uint32_t ksel  = (uint32_t)(lane >> 3);
    const uint32_t k_row = (uint32_t)((ksel >> 1) * 8 + (lane & 7));
    const uint32_t k_k8  = (uint32_t)((ksel & 1) * 16);

    for (int i = 0; i < SENC / 64; i++) {
        const int k0 = i * 64, st = i & 1;
        if (i + 1 < SENC / 64) issue((i + 1) * 64, (i + 1) & 1);
        CP_COMMIT();
        CP_WAIT1();
        __syncthreads();

        const uint32_t kbase = sb + st * 36864;
        const uint32_t vbase = kbase + 18432;

        // ---- S = Q K^T (3-pass) ----
        float sacc[8][4];
#pragma unroll
        for (int ni = 0; ni < 8; ni++)
#pragma unroll
            for (int k = 0; k < 4; k++) sacc[ni][k] = 0.f;
#pragma unroll
        for (int ks = 0; ks < 4; ks++) {
#pragma unroll
            for (int p = 0; p < 4; p++) {
                uint32_t ka = kbase + (k_row + p * 16) * 144 + ks * 32 + k_k8;
                uint32_t rh[4], rl[4];
                ldmx4(rh, ka);
                ldmx4(rl, ka + 9216);
                mma_bf16(sacc[2 * p],     qh[ks], &rh[0]);
                mma_bf16(sacc[2 * p],     ql[ks], &rh[0]);
                mma_bf16(sacc[2 * p],     qh[ks], &rl[0]);
                mma_bf16(sacc[2 * p + 1], qh[ks], &rh[2]);
                mma_bf16(sacc[2 * p + 1], ql[ks], &rh[2]);
                mma_bf16(sacc[2 * p + 1], qh[ks], &rl[2]);
            }
        }

        // ---- mask ----
#pragma unroll
        for (int ni = 0; ni < 8; ni++) {
            uint2 mw = *(const uint2*)(mk + k0 + 8 * ni + 2 * tq);
            if (mw.x) { sacc[ni][0] = -1e30f; sacc[ni][2] = -1e30f; }
            if (mw.y) { sacc[ni][1] = -1e30f; sacc[ni][3] = -1e30f; }
        }

        // ---- online softmax (base-2) ----
        float v0 = -1e30f, v1 = -1e30f;
#pragma unroll
        for (int ni = 0; ni < 8; ni++) {
            v0 = fmaxf(v0, fmaxf(sacc[ni][0], sacc[ni][1]));
            v1 = fmaxf(v1, fmaxf(sacc[ni][2], sacc[ni][3]));
        }
        v0 = fmaxf(v0, __shfl_xor_sync(0xffffffffu, v0, 1));
        v0 = fmaxf(v0, __shfl_xor_sync(0xffffffffu, v0, 2));
        v1 = fmaxf(v1, __shfl_xor_sync(0xffffffffu, v1, 1));
        v1 = fmaxf(v1, __shfl_xor_sync(0xffffffffu, v1, 2));
        float mn0 = fmaxf(m0, v0), mn1 = fmaxf(m1, v1);
        float al0 = exp2p(m0 - mn0), al1 = exp2p(m1 - mn1);
        m0 = mn0; m1 = mn1;

        float rs0 = 0.f, rs1 = 0.f;
#pragma unroll
        for (int ni = 0; ni < 8; ni++) {
            sacc[ni][0] = exp2p(sacc[ni][0] - mn0); rs0 += sacc[ni][0];
            sacc[ni][1] = exp2p(sacc[ni][1] - mn0); rs0 += sacc[ni][1];
            sacc[ni][2] = exp2p(sacc[ni][2] - mn1); rs1 += sacc[ni][2];
            sacc[ni][3] = exp2p(sacc[ni][3] - mn1); rs1 += sacc[ni][3];
        }
        rs0 += __shfl_xor_sync(0xffffffffu, rs0, 1);
        rs0 += __shfl_xor_sync(0xffffffffu, rs0, 2);
        rs1 += __shfl_xor_sync(0xffffffffu, rs1, 1);
        rs1 += __shfl_xor_sync(0xffffffffu, rs1, 2);
        l0 = l0 * al0 + rs0;
        l1 = l1 * al1 + rs1;
#pragma unroll
        for (int ni = 0; ni < 8; ni++) {
            oacc[ni][0] *= al0; oacc[ni][1] *= al0;
            oacc[ni][2] *= al1; oacc[ni][3] *= al1;
        }

        // ---- P fragments ----
        uint32_t pah[4][4], pal[4][4];
#pragma unroll
        for (int j = 0; j < 4; j++) {
            pah[j][0] = pack_hi2(sacc[2 * j][0], sacc[2 * j][1]);
            pal[j][0] = pack_lo2(sacc[2 * j][0], sacc[2 * j][1]);
            pah[j][1] = pack_hi2(sacc[2 * j][2], sacc[2 * j][3]);
            pal[j][1] = pack_lo2(sacc[2 * j][2], sacc[2 * j][3]);
            pah[j][2] = pack_hi2(sacc[2 * j + 1][0], sacc[2 * j + 1][1]);
            pal[j][2] = pack_lo2(sacc[2 * j + 1][0], sacc[2 * j + 1][1]);
            pah[j][3] = pack_hi2(sacc[2 * j + 1][2], sacc[2 * j + 1][3]);
            pal[j][3] = pack_lo2(sacc[2 * j + 1][2], sacc[2 * j + 1][3]);
        }

        // ---- O += P V (3-pass), V via ldmatrix.trans ----
#pragma unroll
        for (int j = 0; j < 4; j++) {
            uint32_t rowoff = (uint32_t)((16 * j + (lane & 15)) * 144);
#pragma unroll
            for (int n2 = 0; n2 < 8; n2 += 2) {
                uint32_t va = vbase + rowoff + n2 * 16 + ((lane >> 4) & 1) * 16;
                uint32_t vrh[4], vrl[4];
                ldmx4_trans(vrh, va);
                ldmx4_trans(vrl, va + 9216);
                mma_bf16(oacc[n2],     pah[j], &vrh[0]);
                mma_bf16(oacc[n2],     pal[j], &vrh[0]);
                mma_bf16(oacc[n2],     pah[j], &vrl[0]);
                mma_bf16(oacc[n2 + 1], pah[j], &vrh[2]);
                mma_bf16(oacc[n2 + 1], pal[j], &vrh[2]);
                mma_bf16(oacc[n2 + 1], pah[j], &vrl[2]);
            }
        }
        __syncthreads();
    }

    // ---- normalize + write packed X ----
    float inv0 = 1.0f / l0, inv1 = 1.0f / l1;
    const size_t row0 = qrow + g;
#pragma unroll
    for (int ni = 0; ni < 8; ni++) {
        size_t cp = (size_t)(h * 32 + ni * 4 + tq);
        float x0 = oacc[ni][0] * inv0, y0 = oacc[ni][1] * inv0;
        float x1 = oacc[ni][2] * inv1, y1 = oacc[ni][3] * inv1;
        g_Xh[row0 * 512 + cp]       = pack_hi2(x0, y0);
        g_Xl[row0 * 512 + cp]       = pack_lo2(x0, y0);
        g_Xh[(row0 + 8) * 512 + cp] = pack_hi2(x1, y1);
        g_Xl[(row0 + 8) * 512 + cp] = pack_lo2(x1, y1);
    }
}

// ============================ Launch ============================
extern "C" void kernel_launch(void* const* d_in, const int* in_sizes, int n_in,
                              void* d_out, int out_size)
{
    const float*        enc      = (const float*)d_in[0];
    const unsigned int* enc_mask = (const unsigned int*)d_in[1];
    const float*        dec      = (const float*)d_in[2];
    const float*        q_w      = (const float*)d_in[3];
    const float*        q_b      = (const float*)d_in[4];
    const float*        k_w      = (const float*)d_in[5];
    const float*        k_b      = (const float*)d_in[6];
    const float*        v_w      = (const float*)d_in[7];
    const float*        v_b      = (const float*)d_in[8];
    const float*        o_w      = (const float*)d_in[9];
    const float*        o_b      = (const float*)d_in[10];
    float*              out      = (float*)d_out;

    uint32_t *pdech, *pdecl, *pench, *pencl, *pwth, *pwtl;
    uint32_t *pQh, *pQl, *pKh, *pKl, *pVh, *pVl, *pXh, *pXl;
    cudaGetSymbolAddress((void**)&pdech, g_dech);
    cudaGetSymbolAddress((void**)&pdecl, g_decl);
    cudaGetSymbolAddress((void**)&pench, g_ench);
    cudaGetSymbolAddress((void**)&pencl, g_encl);
    cudaGetSymbolAddress((void**)&pwth,  g_wth);
    cudaGetSymbolAddress((void**)&pwtl,  g_wtl);
    cudaGetSymbolAddress((void**)&pQh,   g_Qh);
    cudaGetSymbolAddress((void**)&pQl,   g_Ql);
    cudaGetSymbolAddress((void**)&pKh,   g_Kh);
    cudaGetSymbolAddress((void**)&pKl,   g_Kl);
    cudaGetSymbolAddress((void**)&pVh,   g_Vh);
    cudaGetSymbolAddress((void**)&pVl,   g_Vl);
    cudaGetSymbolAddress((void**)&pXh,   g_Xh);
    cudaGetSymbolAddress((void**)&pXl,   g_Xl);

    const size_t WSZ = 1024 * 512;

    cudaFuncSetAttribute(hgemm, cudaFuncAttributeMaxDynamicSharedMemorySize, 81920);
    cudaFuncSetAttribute(attn_mma, cudaFuncAttributeMaxDynamicSharedMemorySize, ATTN_SMEM);

    // launches 1-2: fused converts
    conv_act_all<<<(4096 + 8192) * 512 / 256, 256>>>(dec, enc, pdech, pdecl, pench, pencl);
    conv_wt_all<<<dim3(32, 16, 4), 256>>>(q_w, k_w, v_w, o_w, pwth, pwtl);

    // launches 3-5: projections
    hgemm<<<dim3(8, 32), 256, 81920>>>(pdech, pdecl, pwth + 0 * WSZ, pwtl + 0 * WSZ,
                                       q_b, nullptr, pQh, pQl, CS);
    hgemm<<<dim3(8, 64), 256, 81920>>>(pench, pencl, pwth + 1 * WSZ, pwtl + 1 * WSZ,
                                       k_b, nullptr, pKh, pKl, 1.0f);
    hgemm<<<dim3(8, 64), 256, 81920>>>(pench, pencl, pwth + 2 * WSZ, pwtl + 2 * WSZ,
                                       v_b, nullptr, pVh, pVl, 1.0f);

    // launch 6: attention (ncu -s 5 -c 1 captures this)
    attn_mma<<<dim3(SDEC / 64, NH, BB), 128, ATTN_SMEM>>>(enc_mask);

    // launch 7: output projection
    hgemm<<<dim3(8, 32), 256, 81920>>>(pXh, pXl, pwth + 3 * WSZ, pwtl + 3 * WSZ,
                                       o_b, out, nullptr, nullptr, 1.0f);
}

// round 9
// speedup vs baseline: 3.1280x; 1.1635x over previous
#include <cuda_runtime.h>
#include <cuda_bf16.h>
#include <cstdint>

#define BB 4
#define SENC 2048
#define SDEC 1024
#define DIM 1024
#define NH 16
#define HD 64
#define CS (0.125f * 1.44269504088896f)   // 1/sqrt(64) * log2(e)
#define WSZ (1024 * 512)

// ================= persistent packed-bf16 hi/lo scratch (uint32 = 2 bf16) ==
__device__ uint32_t g_dech[4096*512], g_decl[4096*512];
__device__ uint32_t g_ench[8192*512], g_encl[8192*512];   // compacted key order
__device__ uint32_t g_wth[4][1024*512], g_wtl[4][1024*512];
__device__ uint32_t g_Qh[4096*512],  g_Ql[4096*512];      // CS pre-folded
__device__ uint32_t g_Kh[8192*512],  g_Kl[8192*512];      // compacted
__device__ uint32_t g_Vh[8192*512],  g_Vl[8192*512];      // compacted
__device__ uint32_t g_Xh[4096*512],  g_Xl[4096*512];
__device__ int g_idx[BB * SENC];
__device__ int g_cnt[BB];

// ============================ helpers ============================
__device__ __forceinline__ uint32_t smem_u32(const void* p) {
    uint32_t a;
    asm("{ .reg .u64 t; cvta.to.shared.u64 t, %1; cvt.u32.u64 %0, t; }" : "=r"(a) : "l"(p));
    return a;
}
__device__ __forceinline__ uint32_t pack_hi2(float x, float y) {
    __nv_bfloat16 a = __float2bfloat16_rn(x), b = __float2bfloat16_rn(y);
    return (uint32_t)__bfloat16_as_ushort(a) | ((uint32_t)__bfloat16_as_ushort(b) << 16);
}
__device__ __forceinline__ uint32_t pack_lo2(float x, float y) {
    __nv_bfloat16 a = __float2bfloat16_rn(x), b = __float2bfloat16_rn(y);
    __nv_bfloat16 la = __float2bfloat16_rn(x - __bfloat162float(a));
    __nv_bfloat16 lb = __float2bfloat16_rn(y - __bfloat162float(b));
    return (uint32_t)__bfloat16_as_ushort(la) | ((uint32_t)__bfloat16_as_ushort(lb) << 16);
}
__device__ __forceinline__ void mma_bf16(float* d, const uint32_t* a, const uint32_t* b) {
    asm volatile("mma.sync.aligned.m16n8k16.row.col.f32.bf16.bf16.f32 "
        "{%0,%1,%2,%3}, {%4,%5,%6,%7}, {%8,%9}, {%0,%1,%2,%3};"
        : "+f"(d[0]), "+f"(d[1]), "+f"(d[2]), "+f"(d[3])
        : "r"(a[0]), "r"(a[1]), "r"(a[2]), "r"(a[3]), "r"(b[0]), "r"(b[1]));
}
__device__ __forceinline__ void ldmx4(uint32_t* r, uint32_t addr) {
    asm volatile("ldmatrix.sync.aligned.m8n8.x4.shared.b16 {%0,%1,%2,%3}, [%4];"
        : "=r"(r[0]), "=r"(r[1]), "=r"(r[2]), "=r"(r[3]) : "r"(addr));
}
__device__ __forceinline__ void ldmx4_trans(uint32_t* r, uint32_t addr) {
    asm volatile("ldmatrix.sync.aligned.m8n8.x4.trans.shared.b16 {%0,%1,%2,%3}, [%4];"
        : "=r"(r[0]), "=r"(r[1]), "=r"(r[2]), "=r"(r[3]) : "r"(addr));
}
__device__ __forceinline__ float exp2p(float u) {
    u = fmaxf(u, -60.0f);
    float n = rintf(u);
    float f = u - n;
    float p = 0.0013333558f;
    p = fmaf(p, f, 0.0096181291f);
    p = fmaf(p, f, 0.0555041087f);
    p = fmaf(p, f, 0.2402265070f);
    p = fmaf(p, f, 0.6931471806f);
    p = fmaf(p, f, 1.0f);
    int sb = (__float2int_rn(n) + 127) << 23;
    return p * __int_as_float(sb);
}
#define CP16(dst, src) \
    asm volatile("cp.async.cg.shared.global [%0], [%1], 16;" :: "r"(dst), "l"(src) : "memory")
#define CP_COMMIT() asm volatile("cp.async.commit_group;" ::: "memory")
#define CP_WAIT1()  asm volatile("cp.async.wait_group 1;" ::: "memory")

// ============================ setup kernels ============================
// stable compaction of unmasked key indices, one block per batch
__global__ __launch_bounds__(1024) void scan_mask(const unsigned int* __restrict__ mask)
{
    __shared__ int ps[1024];
    const int b = blockIdx.x, t = threadIdx.x;
    const unsigned int* m = mask + b * SENC;
    g_idx[b * SENC + 2 * t]     = 0;
    g_idx[b * SENC + 2 * t + 1] = 0;
    int f0 = (m[2 * t] == 0u) ? 1 : 0;
    int f1 = (m[2 * t + 1] == 0u) ? 1 : 0;
    ps[t] = f0 + f1;
    __syncthreads();
    for (int d = 1; d < 1024; d <<= 1) {
        int v = ps[t];
        int add = (t >= d) ? ps[t - d] : 0;
        __syncthreads();
        ps[t] = v + add;
        __syncthreads();
    }
    int excl = (t > 0) ? ps[t - 1] : 0;
    if (f0) g_idx[b * SENC + excl] = 2 * t;
    if (f1) g_idx[b * SENC + excl + f0] = 2 * t + 1;
    if (t == 1023) g_cnt[b] = ps[1023];
}

__global__ __launch_bounds__(256) void conv_dec(
    const float* __restrict__ dec, uint32_t* __restrict__ DH, uint32_t* __restrict__ DL)
{
    int i = blockIdx.x * 256 + threadIdx.x;
    float2 v = ((const float2*)dec)[i];
    DH[i] = pack_hi2(v.x, v.y);
    DL[i] = pack_lo2(v.x, v.y);
}

// gather enc rows into compacted key order while converting
__global__ __launch_bounds__(256) void conv_enc_gather(
    const float* __restrict__ enc, uint32_t* __restrict__ EH, uint32_t* __restrict__ EL)
{
    int i = blockIdx.x * 256 + threadIdx.x;       // over 8192*512
    int r = i >> 9, c = i & 511;
    int b = r >> 11, j = r & 2047;
    int src = b * SENC + g_idx[b * SENC + j];
    float2 v = ((const float2*)enc)[(size_t)src * 512 + c];
    EH[i] = pack_hi2(v.x, v.y);
    EL[i] = pack_lo2(v.x, v.y);
}

__global__ __launch_bounds__(256) void conv_wt_all(
    const float* __restrict__ W0, const float* __restrict__ W1,
    const float* __restrict__ W2, const float* __restrict__ W3,
    uint32_t* __restrict__ Th, uint32_t* __restrict__ Tl)
{
    __shared__ float tile[64][33];
    const float* W = (blockIdx.z == 0) ? W0 : (blockIdx.z == 1) ? W1
                   : (blockIdx.z == 2) ? W2 : W3;
    uint32_t* Thz = Th + (size_t)blockIdx.z * WSZ;
    uint32_t* Tlz = Tl + (size_t)blockIdx.z * WSZ;
    int k0 = blockIdx.y * 64, n0 = blockIdx.x * 32;
    int tx = threadIdx.x & 31, ty = threadIdx.x >> 5;
    for (int r = ty; r < 64; r += 8)
        tile[r][tx] = W[(size_t)(k0 + r) * 1024 + n0 + tx];
    __syncthreads();
    for (int nn = ty; nn < 32; nn += 8) {
        float a = tile[2 * tx][nn], b = tile[2 * tx + 1][nn];
        Thz[(size_t)(n0 + nn) * 512 + (k0 >> 1) + tx] = pack_hi2(a, b);
        Tlz[(size_t)(n0 + nn) * 512 + (k0 >> 1) + tx] = pack_lo2(a, b);
    }
}

// ============================ shared GEMM body ============================
#define AST 20

__device__ __forceinline__ void gemm_body(
    const uint32_t* __restrict__ Ah, const uint32_t* __restrict__ Al,
    const uint32_t* __restrict__ Wh, const uint32_t* __restrict__ Wl,
    const float* __restrict__ bias,
    float* __restrict__ Cf, uint32_t* __restrict__ Ch, uint32_t* __restrict__ Cl,
    float scale, int bm, int bn, uint32_t* smu)
{
    const uint32_t sb = smem_u32(smu);
    const int t = threadIdx.x, lane = t & 31, wid = t >> 5;
    const int g = lane >> 2, tq = lane & 3;
    const int wm = wid & 1, wn = wid >> 1;

    float acc[4][4][4];
#pragma unroll
    for (int i = 0; i < 4; i++)
#pragma unroll
        for (int j = 0; j < 4; j++)
#pragma unroll
            for (int k = 0; k < 4; k++) acc[i][j][k] = 0.f;

    auto issue = [&](int kb, int st) {
        const uint32_t base = sb + st * 40960;
        const int row = t >> 2, ch = t & 3;
#pragma unroll
        for (int c = 0; c < 8; c++) {
            int tile = c >> 1;
            int r = (c & 1) * 64 + row;
            const uint32_t* src = (tile == 0) ? Ah : (tile == 1) ? Al
                                : (tile == 2) ? Wh : Wl;
            int grow = ((tile < 2) ? bm : bn) + r;
            CP16(base + (uint32_t)(tile * 2560 + r * AST + ch * 4) * 4,
                 src + (size_t)grow * 512 + (kb >> 1) + ch * 4);
        }
    };

    issue(0, 0);
    CP_COMMIT();

    const uint32_t a_row = (uint32_t)(wm * 64 + (lane & 15));
    const uint32_t a_k8  = (uint32_t)((lane >> 4) * 16);
    const uint32_t bsel  = (uint32_t)(lane >> 3);
    const uint32_t b_row = (uint32_t)(wn * 32 + (bsel >> 1) * 8 + (lane & 7));
    const uint32_t b_k8  = (uint32_t)((bsel & 1) * 16);

    for (int i = 0; i < 32; i++) {
        if (i + 1 < 32) issue((i + 1) * 32, (i + 1) & 1);
        CP_COMMIT();
        CP_WAIT1();
        __syncthreads();

        const uint32_t stb = sb + (i & 1) * 40960;

#pragma unroll
        for (int ks = 0; ks < 2; ks++) {
            uint32_t ah[4][4], al[4][4], bh[4][2], bl[4][2];
#pragma unroll
            for (int mi = 0; mi < 4; mi++) {
                uint32_t aa = stb + (a_row + mi * 16) * (AST * 4) + ks * 32 + a_k8;
                ldmx4(ah[mi], aa);
                ldmx4(al[mi], aa + 10240);
            }
#pragma unroll
            for (int p = 0; p < 2; p++) {
                uint32_t ba = stb + 20480 + (b_row + p * 16) * (AST * 4) + ks * 32 + b_k8;
                uint32_t rh[4], rl[4];
                ldmx4(rh, ba);
                ldmx4(rl, ba + 10240);
                bh[2 * p][0] = rh[0]; bh[2 * p][1] = rh[1];
                bh[2 * p + 1][0] = rh[2]; bh[2 * p + 1][1] = rh[3];
                bl[2 * p][0] = rl[0]; bl[2 * p][1] = rl[1];
                bl[2 * p + 1][0] = rl[2]; bl[2 * p + 1][1] = rl[3];
            }
#pragma unroll
            for (int mi = 0; mi < 4; mi++)
#pragma unroll
                for (int ni = 0; ni < 4; ni++) {
                    mma_bf16(acc[mi][ni], ah[mi], bh[ni]);
                    mma_bf16(acc[mi][ni], ah[mi], bl[ni]);
                    mma_bf16(acc[mi][ni], al[mi], bh[ni]);
                }
        }
        __syncthreads();
    }

#pragma unroll
    for (int mi = 0; mi < 4; mi++) {
        int r0 = bm + wm * 64 + mi * 16 + g;
#pragma unroll
        for (int ni = 0; ni < 4; ni++) {
            int c = bn + wn * 32 + ni * 8 + 2 * tq;
            float2 bb = *(const float2*)(bias + c);
            float* d = acc[mi][ni];
            if (Cf) {
                *(float2*)(Cf + (size_t)r0 * 1024 + c) =
                    make_float2(d[0] + bb.x, d[1] + bb.y);
                *(float2*)(Cf + (size_t)(r0 + 8) * 1024 + c) =
                    make_float2(d[2] + bb.x, d[3] + bb.y);
            } else {
                float x0 = (d[0] + bb.x) * scale, y0 = (d[1] + bb.y) * scale;
                float x1 = (d[2] + bb.x) * scale, y1 = (d[3] + bb.y) * scale;
                size_t cp = (size_t)(c >> 1);
                Ch[(size_t)r0 * 512 + cp]       = pack_hi2(x0, y0);
                Cl[(size_t)r0 * 512 + cp]       = pack_lo2(x0, y0);
                Ch[(size_t)(r0 + 8) * 512 + cp] = pack_hi2(x1, y1);
                Cl[(size_t)(r0 + 8) * 512 + cp] = pack_lo2(x1, y1);
            }
        }
    }
}

// fused Q/K/V projections; K/V tiles beyond the compacted count exit early
__global__ __launch_bounds__(256) void hgemm_qkv(
    const uint32_t* __restrict__ dech, const uint32_t* __restrict__ decl,
    const uint32_t* __restrict__ ench, const uint32_t* __restrict__ encl,
    const uint32_t* __restrict__ wth, const uint32_t* __restrict__ wtl,
    const float* __restrict__ q_b, const float* __restrict__ k_b,
    const float* __restrict__ v_b,
    uint32_t* __restrict__ Qh, uint32_t* __restrict__ Ql,
    uint32_t* __restrict__ Kh, uint32_t* __restrict__ Kl,
    uint32_t* __restrict__ Vh, uint32_t* __restrict__ Vl)
{
    extern __shared__ uint32_t smu[];
    const int yt = blockIdx.y;
    const int bn = blockIdx.x * 128;
    if (yt < 32) {
        gemm_body(dech, decl, wth, wtl, q_b, nullptr, Qh, Ql, CS, yt * 128, bn, smu);
    } else if (yt < 96) {
        int bm = (yt - 32) * 128;
        int b = bm >> 11;
        if ((bm & 2047) >= ((g_cnt[b] + 127) & ~127)) return;
        gemm_body(ench, encl, wth + WSZ, wtl + WSZ, k_b, nullptr, Kh, Kl, 1.0f, bm, bn, smu);
    } else {
        int bm = (yt - 96) * 128;
        int b = bm >> 11;
        if ((bm & 2047) >= ((g_cnt[b] + 127) & ~127)) return;
        gemm_body(ench, encl, wth + 2 * WSZ, wtl + 2 * WSZ, v_b, nullptr, Vh, Vl, 1.0f, bm, bn, smu);
    }
}

__global__ __launch_bounds__(256) void hgemm_o(
    const uint32_t* __restrict__ Xh, const uint32_t* __restrict__ Xl,
    const uint32_t* __restrict__ Wh, const uint32_t* __restrict__ Wl,
    const float* __restrict__ bias, float* __restrict__ Cf)
{
    extern __shared__ uint32_t smu[];
    gemm_body(Xh, Xl, Wh, Wl, bias, Cf, nullptr, nullptr, 1.0f,
              blockIdx.y * 128, blockIdx.x * 128, smu);
}

// ============================ FA2 attention (compacted keys) =============
#define ATTN_SMEM (2 * 36864)

__global__ __launch_bounds__(128, 2) void attn_mma()
{
    extern __shared__ uint32_t smu[];
    const uint32_t sb = smem_u32(smu);
    const int t = threadIdx.x, w = t >> 5, lane = t & 31;
    const int g = lane >> 2, tq = lane & 3;
    const int qt = blockIdx.x, h = blockIdx.y, b = blockIdx.z;
    const int q0 = qt * 64;
    const int cntb = g_cnt[b];
    const int nt = (cntb + 63) >> 6;

    const size_t qrow = (size_t)(b * SDEC + q0 + 16 * w);
    uint32_t qh[4][4], ql[4][4];
#pragma unroll
    for (int ks = 0; ks < 4; ks++) {
        size_t p0 = (qrow + g) * 512 + h * 32 + ks * 8 + tq;
        size_t p1 = (qrow + g + 8) * 512 + h * 32 + ks * 8 + tq;
        qh[ks][0] = g_Qh[p0]; qh[ks][1] = g_Qh[p1];
        qh[ks][2] = g_Qh[p0 + 4]; qh[ks][3] = g_Qh[p1 + 4];
        ql[ks][0] = g_Ql[p0]; ql[ks][1] = g_Ql[p1];
        ql[ks][2] = g_Ql[p0 + 4]; ql[ks][3] = g_Ql[p1 + 4];
    }

    float m0 = -1e30f, m1 = -1e30f, l0 = 0.f, l1 = 0.f;
    float oacc[8][4];
#pragma unroll
    for (int ni = 0; ni < 8; ni++)
#pragma unroll
        for (int k = 0; k < 4; k++) oacc[ni][k] = 0.f;

    auto issue = [&](int kb, int st) {
        const uint32_t base = sb + st * 36864;
        const uint32_t* srcs[4] = {g_Kh, g_Kl, g_Vh, g_Vl};
        const int keyl = t >> 3, ch = t & 7;
#pragma unroll
        for (int c = 0; c < 16; c++) {
            int tile = c >> 2;
            int key = (c & 3) * 16 + keyl;
            CP16(base + (uint32_t)(tile * 9216 + key * 144 + ch * 16),
                 srcs[tile] + (size_t)(b * SENC + kb + key) * 512 + h * 32 + ch * 4);
        }
    };

    issue(0, 0);
    CP_COMMIT();

    const uint32_t ksel  = (uint32_t)(lane >> 3);
    const uint32_t k_row = (uint32_t)((ksel >> 1) * 8 + (lane & 7));
    const uint32_t k_k8  = (uint32_t)((ksel & 1) * 16);

    for (int i = 0; i < nt; i++) {
        const int k0 = i * 64, st = i & 1;
        if (i + 1 < nt) issue((i + 1) * 64, (i + 1) & 1);
        CP_COMMIT();
        CP_WAIT1();
        __syncthreads();

        const uint32_t kbase = sb + st * 36864;
        const uint32_t vbase = kbase + 18432;

        // ---- S = Q K^T (3-pass) ----
        float sacc[8][4];
#pragma unroll
        for (int ni = 0; ni < 8; ni++)
#pragma unroll
            for (int k = 0; k < 4; k++) sacc[ni][k] = 0.f;
#pragma unroll
        for (int ks = 0; ks < 4; ks++) {
#pragma unroll
            for (int p = 0; p < 4; p++) {
                uint32_t ka = kbase + (k_row + p * 16) * 144 + ks * 32 + k_k8;
                uint32_t rh[4], rl[4];
                ldmx4(rh, ka);
                ldmx4(rl, ka + 9216);
                mma_bf16(sacc[2 * p],     qh[ks], &rh[0]);
                mma_bf16(sacc[2 * p],     ql[ks], &rh[0]);
                mma_bf16(sacc[2 * p],     qh[ks], &rl[0]);
                mma_bf16(sacc[2 * p + 1], qh[ks], &rh[2]);
                mma_bf16(sacc[2 * p + 1], ql[ks], &rh[2]);
                mma_bf16(sacc[2 * p + 1], qh[ks], &rl[2]);
            }
        }

        // ---- last-tile bounds mask ----
        if (k0 + 64 > cntb) {
#pragma unroll
            for (int ni = 0; ni < 8; ni++) {
                int c0 = k0 + 8 * ni + 2 * tq;
                if (c0 >= cntb)     { sacc[ni][0] = -1e30f; sacc[ni][2] = -1e30f; }
                if (c0 + 1 >= cntb) { sacc[ni][1] = -1e30f; sacc[ni][3] = -1e30f; }
            }
        }

        // ---- online softmax (base-2) ----
        float v0 = -1e30f, v1 = -1e30f;
#pragma unroll
        for (int ni = 0; ni < 8; ni++) {
            v0 = fmaxf(v0, fmaxf(sacc[ni][0], sacc[ni][1]));
            v1 = fmaxf(v1, fmaxf(sacc[ni][2], sacc[ni][3]));
        }
        v0 = fmaxf(v0, __shfl_xor_sync(0xffffffffu, v0, 1));
        v0 = fmaxf(v0, __shfl_xor_sync(0xffffffffu, v0, 2));
        v1 = fmaxf(v1, __shfl_xor_sync(0xffffffffu, v1, 1));
        v1 = fmaxf(v1, __shfl_xor_sync(0xffffffffu, v1, 2));
        float mn0 = fmaxf(m0, v0), mn1 = fmaxf(m1, v1);
        float al0 = exp2p(m0 - mn0), al1 = exp2p(m1 - mn1);
        m0 = mn0; m1 = mn1;

        float rs0 = 0.f, rs1 = 0.f;
#pragma unroll
        for (int ni = 0; ni < 8; ni++) {
            sacc[ni][0] = exp2p(sacc[ni][0] - mn0); rs0 += sacc[ni][0];
            sacc[ni][1] = exp2p(sacc[ni][1] - mn0); rs0 += sacc[ni][1];
            sacc[ni][2] = exp2p(sacc[ni][2] - mn1); rs1 += sacc[ni][2];
            sacc[ni][3] = exp2p(sacc[ni][3] - mn1); rs1 += sacc[ni][3];
        }
        rs0 += __shfl_xor_sync(0xffffffffu, rs0, 1);
        rs0 += __shfl_xor_sync(0xffffffffu, rs0, 2);
        rs1 += __shfl_xor_sync(0xffffffffu, rs1, 1);
        rs1 += __shfl_xor_sync(0xffffffffu, rs1, 2);
        l0 = l0 * al0 + rs0;
        l1 = l1 * al1 + rs1;
#pragma unroll
        for (int ni = 0; ni < 8; ni++) {
            oacc[ni][0] *= al0; oacc[ni][1] *= al0;
            oacc[ni][2] *= al1; oacc[ni][3] *= al1;
        }

        // ---- P fragments ----
        uint32_t pah[4][4], pal[4][4];
#pragma unroll
        for (int j = 0; j < 4; j++) {
            pah[j][0] = pack_hi2(sacc[2 * j][0], sacc[2 * j][1]);
            pal[j][0] = pack_lo2(sacc[2 * j][0], sacc[2 * j][1]);
            pah[j][1] = pack_hi2(sacc[2 * j][2], sacc[2 * j][3]);
            pal[j][1] = pack_lo2(sacc[2 * j][2], sacc[2 * j][3]);
            pah[j][2] = pack_hi2(sacc[2 * j + 1][0], sacc[2 * j + 1][1]);
            pal[j][2] = pack_lo2(sacc[2 * j + 1][0], sacc[2 * j + 1][1]);
            pah[j][3] = pack_hi2(sacc[2 * j + 1][2], sacc[2 * j + 1][3]);
            pal[j][3] = pack_lo2(sacc[2 * j + 1][2], sacc[2 * j + 1][3]);
        }

        // ---- O += P V (3-pass), V via ldmatrix.trans ----
#pragma unroll
        for (int j = 0; j < 4; j++) {
            uint32_t rowoff = (uint32_t)((16 * j + (lane & 15)) * 144);
#pragma unroll
            for (int n2 = 0; n2 < 8; n2 += 2) {
                uint32_t va = vbase + rowoff + n2 * 16 + ((lane >> 4) & 1) * 16;
                uint32_t vrh[4], vrl[4];
                ldmx4_trans(vrh, va);
                ldmx4_trans(vrl, va + 9216);
                mma_bf16(oacc[n2],     pah[j], &vrh[0]);
                mma_bf16(oacc[n2],     pal[j], &vrh[0]);
                mma_bf16(oacc[n2],     pah[j], &vrl[0]);
                mma_bf16(oacc[n2 + 1], pah[j], &vrh[2]);
                mma_bf16(oacc[n2 + 1], pal[j], &vrh[2]);
                mma_bf16(oacc[n2 + 1], pah[j], &vrl[2]);
            }
        }
        __syncthreads();
    }

    // ---- normalize + write packed X ----
    float inv0 = 1.0f / l0, inv1 = 1.0f / l1;
    const size_t row0 = qrow + g;
#pragma unroll
    for (int ni = 0; ni < 8; ni++) {
        size_t cp = (size_t)(h * 32 + ni * 4 + tq);
        float x0 = oacc[ni][0] * inv0, y0 = oacc[ni][1] * inv0;
        float x1 = oacc[ni][2] * inv1, y1 = oacc[ni][3] * inv1;
        g_Xh[row0 * 512 + cp]       = pack_hi2(x0, y0);
        g_Xl[row0 * 512 + cp]       = pack_lo2(x0, y0);
        g_Xh[(row0 + 8) * 512 + cp] = pack_hi2(x1, y1);
        g_Xl[(row0 + 8) * 512 + cp] = pack_lo2(x1, y1);
    }
}

// ============================ Launch ============================
extern "C" void kernel_launch(void* const* d_in, const int* in_sizes, int n_in,
                              void* d_out, int out_size)
{
    const float*        enc      = (const float*)d_in[0];
    const unsigned int* enc_mask = (const unsigned int*)d_in[1];
    const float*        dec      = (const float*)d_in[2];
    const float*        q_w      = (const float*)d_in[3];
    const float*        q_b      = (const float*)d_in[4];
    const float*        k_w      = (const float*)d_in[5];
    const float*        k_b      = (const float*)d_in[6];
    const float*        v_w      = (const float*)d_in[7];
    const float*        v_b      = (const float*)d_in[8];
    const float*        o_w      = (const float*)d_in[9];
    const float*        o_b      = (const float*)d_in[10];
    float*              out      = (float*)d_out;

    uint32_t *pdech, *pdecl, *pench, *pencl, *pwth, *pwtl;
    uint32_t *pQh, *pQl, *pKh, *pKl, *pVh, *pVl, *pXh, *pXl;
    cudaGetSymbolAddress((void**)&pdech, g_dech);
    cudaGetSymbolAddress((void**)&pdecl, g_decl);
    cudaGetSymbolAddress((void**)&pench, g_ench);
    cudaGetSymbolAddress((void**)&pencl, g_encl);
    cudaGetSymbolAddress((void**)&pwth,  g_wth);
    cudaGetSymbolAddress((void**)&pwtl,  g_wtl);
    cudaGetSymbolAddress((void**)&pQh,   g_Qh);
    cudaGetSymbolAddress((void**)&pQl,   g_Ql);
    cudaGetSymbolAddress((void**)&pKh,   g_Kh);
    cudaGetSymbolAddress((void**)&pKl,   g_Kl);
    cudaGetSymbolAddress((void**)&pVh,   g_Vh);
    cudaGetSymbolAddress((void**)&pVl,   g_Vl);
    cudaGetSymbolAddress((void**)&pXh,   g_Xh);
    cudaGetSymbolAddress((void**)&pXl,   g_Xl);

    cudaFuncSetAttribute(hgemm_qkv, cudaFuncAttributeMaxDynamicSharedMemorySize, 81920);
    cudaFuncSetAttribute(hgemm_o,   cudaFuncAttributeMaxDynamicSharedMemorySize, 81920);
    cudaFuncSetAttribute(attn_mma,  cudaFuncAttributeMaxDynamicSharedMemorySize, ATTN_SMEM);

    // 1: weights  2: mask scan  3: dec convert  4: enc gather-convert
    conv_wt_all<<<dim3(32, 16, 4), 256>>>(q_w, k_w, v_w, o_w, pwth, pwtl);
    scan_mask<<<BB, 1024>>>(enc_mask);
    conv_dec<<<4096 * 512 / 256, 256>>>(dec, pdech, pdecl);
    conv_enc_gather<<<8192 * 512 / 256, 256>>>(enc, pench, pencl);

    // 5: fused Q/K/V projections
    hgemm_qkv<<<dim3(8, 160), 256, 81920>>>(pdech, pdecl, pench, pencl, pwth, pwtl,
                                            q_b, k_b, v_b, pQh, pQl, pKh, pKl, pVh, pVl);

    // 6: attention (ncu -s 5 -c 1 captures this)
    attn_mma<<<dim3(SDEC / 64, NH, BB), 128, ATTN_SMEM>>>();

    // 7: output projection
    hgemm_o<<<dim3(8, 32), 256, 81920>>>(pXh, pXl, pwth + 3 * WSZ, pwtl + 3 * WSZ, o_b, out);
}